// round 1
// baseline (speedup 1.0000x reference)
#include <cuda_runtime.h>
#include <math.h>

#define B 32
#define T 8192
#define H 192
#define BT (B*T)
#define BINS 10
#define TAILV 5.0f
#define NJ 29

// scratch: residual stream and conv output, layout [b][t][c] (c fastest)
__device__ float g_x[(size_t)BT*H];
__device__ float g_y[(size_t)BT*H];

__device__ __forceinline__ float gelu_exact(float v){
    return 0.5f*v*(1.0f+erff(v*0.70710678118654752f));
}

// ---------------------------------------------------------------------------
// h[b,t,c] = in_w[c]*xa[b,t] + in_b[c]
__global__ void k_init(const float* __restrict__ x,
                       const float* __restrict__ in_w,
                       const float* __restrict__ in_b)
{
    long long idx = (long long)blockIdx.x*256 + threadIdx.x;
    int c = (int)(idx % H);
    long long bt = idx / H;
    int b = (int)(bt >> 13);
    int t = (int)(bt & (T-1));
    float xa = x[((long long)b*2)*T + t];
    g_x[idx] = in_w[c]*xa + in_b[c];
}

__global__ void k_zero(float* __restrict__ out){
    out[(long long)B*2*T + threadIdx.x] = 0.0f;
}

// ---------------------------------------------------------------------------
// depthwise dilated conv (K=3) + LN(channel) + exact gelu. warp per t.
__global__ void __launch_bounds__(256) k_conv(int layer, int dil,
    const float* __restrict__ xmask,
    const float* __restrict__ dw_w, const float* __restrict__ dw_b,
    const float* __restrict__ ln_g, const float* __restrict__ ln_b)
{
    int wid = threadIdx.x >> 5, lane = threadIdx.x & 31;
    long long gidx = (long long)blockIdx.x*8 + wid;
    int b = (int)(gidx >> 13);
    int t = (int)(gidx & (T-1));
    const float* base = g_x + gidx*H;
    int tm = t - dil, tp = t + dil;
    bool hm = (tm >= 0), hp = (tp < T);
    float mm = hm ? xmask[(long long)b*T + tm] : 0.f;
    float m0 = xmask[(long long)b*T + t];
    float mp = hp ? xmask[(long long)b*T + tp] : 0.f;
    const float* bm = base - (long long)dil*H;
    const float* bp = base + (long long)dil*H;
    const float* wbase = dw_w + (long long)layer*H*3;
    const float* bbase = dw_b + layer*H;
    float v[6];
    float s = 0.f, sq = 0.f;
    #pragma unroll
    for(int j=0;j<6;j++){
        int c = lane + 32*j;
        float w0 = wbase[c*3+0], w1 = wbase[c*3+1], w2 = wbase[c*3+2];
        float a0 = hm ? bm[c]*mm : 0.f;
        float a1 = base[c]*m0;
        float a2 = hp ? bp[c]*mp : 0.f;
        float r = w0*a0 + w1*a1 + w2*a2 + bbase[c];
        v[j] = r; s += r; sq += r*r;
    }
    #pragma unroll
    for(int o=16;o>0;o>>=1){
        s  += __shfl_xor_sync(0xffffffffu, s,  o);
        sq += __shfl_xor_sync(0xffffffffu, sq, o);
    }
    float mu = s*(1.0f/H);
    float var = sq*(1.0f/H) - mu*mu;
    float rs = rsqrtf(var + 1e-5f);
    float* outp = g_y + gidx*H;
    const float* gg = ln_g + layer*H;
    const float* gb = ln_b + layer*H;
    #pragma unroll
    for(int j=0;j<6;j++){
        int c = lane + 32*j;
        float yv = (v[j]-mu)*rs*gg[c] + gb[c];
        outp[c] = gelu_exact(yv);
    }
}

// ---------------------------------------------------------------------------
// pointwise 192x192 GEMM + bias + LN(channel) + gelu + residual into g_x.
// BM=192 (all outputs, so LN fuses), BN=64 t-columns. W + Y tiles in smem.
#define GEMM_SMEM_FLOATS (36864 + 12288 + 512 + 128)
#define GEMM_SMEM_BYTES  (GEMM_SMEM_FLOATS*4)

__global__ void __launch_bounds__(256) k_gemm(int layer,
    const float* __restrict__ pw_w, const float* __restrict__ pw_b,
    const float* __restrict__ ln_g, const float* __restrict__ ln_b)
{
    extern __shared__ float sm[];
    float* Wsm = sm;                 // [c*192 + o]
    float* Ysm = sm + H*H;           // [c*64 + tl]
    float* Red = sm + H*H + H*64;    // 512 partials
    float* Mu  = Red + 512;          // 64
    float* Rs  = Mu + 64;            // 64
    int tid = threadIdx.x;
    long long bt0 = (long long)blockIdx.x*64;

    const float* Wg = pw_w + (long long)layer*H*H;
    for(int i=tid;i<H*H;i+=256){
        int o = i/H, c = i - o*H;
        Wsm[c*H + o] = Wg[i];        // transpose: [c][o]
    }
    const float* Yg = g_y + bt0*H;
    for(int i=tid;i<64*H;i+=256){
        int tl = i/H, c = i - tl*H;
        Ysm[c*64 + tl] = Yg[i];      // transpose: [c][t]
    }
    __syncthreads();

    int og = tid & 15, tg = tid >> 4;   // 16 o-groups x 16 t-groups
    float a[12][4];
    #pragma unroll
    for(int k=0;k<12;k++){ a[k][0]=0.f;a[k][1]=0.f;a[k][2]=0.f;a[k][3]=0.f; }
    const float* wp = Wsm + og*4;
    const float* yp = Ysm + tg*4;
    #pragma unroll 2
    for(int c=0;c<H;c++){
        float4 w0 = *(const float4*)(wp + c*H);
        float4 w1 = *(const float4*)(wp + c*H + 64);
        float4 w2 = *(const float4*)(wp + c*H + 128);
        float4 y4 = *(const float4*)(yp + c*64);
        float y0=y4.x, y1=y4.y, y2=y4.z, y3=y4.w;
#define ROWFMA(k, wc) a[k][0]+=(wc)*y0; a[k][1]+=(wc)*y1; a[k][2]+=(wc)*y2; a[k][3]+=(wc)*y3;
        ROWFMA(0,w0.x) ROWFMA(1,w0.y) ROWFMA(2,w0.z) ROWFMA(3,w0.w)
        ROWFMA(4,w1.x) ROWFMA(5,w1.y) ROWFMA(6,w1.z) ROWFMA(7,w1.w)
        ROWFMA(8,w2.x) ROWFMA(9,w2.y) ROWFMA(10,w2.z) ROWFMA(11,w2.w)
#undef ROWFMA
    }
    __syncthreads();   // done with Wsm; overlay Osm on it

    float* Osm = sm;   // [o*67 + tl], 192*67 = 12864 floats < 36864
    const float* pb = pw_b + layer*H;
    #pragma unroll
    for(int k=0;k<12;k++){
        int o = og*4 + (k & 3) + (k >> 2)*64;
        float bias = pb[o];
        #pragma unroll
        for(int s=0;s<4;s++)
            Osm[o*67 + tg*4 + s] = a[k][s] + bias;
    }
    __syncthreads();

    // LN stats: 4 workers per t-column
    {
        int tl = tid & 63, w = tid >> 6;
        float s1=0.f, s2=0.f;
        #pragma unroll 4
        for(int k=0;k<48;k++){
            float v = Osm[(w*48+k)*67 + tl];
            s1 += v; s2 += v*v;
        }
        Red[w*64+tl] = s1;
        Red[256 + w*64+tl] = s2;
    }
    __syncthreads();
    if(tid < 64){
        float s1 = Red[tid]+Red[64+tid]+Red[128+tid]+Red[192+tid];
        float s2 = Red[256+tid]+Red[320+tid]+Red[384+tid]+Red[448+tid];
        float mu = s1*(1.0f/H);
        Mu[tid] = mu;
        Rs[tid] = rsqrtf(s2*(1.0f/H) - mu*mu + 1e-5f);
    }
    __syncthreads();

    float* Xg = g_x + bt0*H;
    const float* lg = ln_g + layer*H;
    const float* lb = ln_b + layer*H;
    for(int e=tid;e<64*H;e+=256){
        int tl = e/H, o = e - tl*H;
        float v = Osm[o*67 + tl];
        float yv = gelu_exact((v - Mu[tl])*Rs[tl]*lg[o] + lb[o]);
        Xg[e] = Xg[e] + yv;
    }
}

// ---------------------------------------------------------------------------
// proj (192->29) + rational-quadratic spline + outputs + logdet
#define SPLINE_SMEM_FLOATS (NJ*H + 128*193)
#define SPLINE_SMEM_BYTES  (SPLINE_SMEM_FLOATS*4)

__global__ void __launch_bounds__(128) k_spline(
    const float* __restrict__ x, const float* __restrict__ xmask,
    const float* __restrict__ proj_w, const float* __restrict__ proj_b,
    float* __restrict__ out)
{
    extern __shared__ float sm[];
    float* Wsm = sm;            // [j*192 + c]
    float* Xsm = sm + NJ*H;     // [tl*193 + c]
    int tid = threadIdx.x;
    long long bt0 = (long long)blockIdx.x*128;

    for(int i=tid;i<NJ*H;i+=128) Wsm[i] = proj_w[i];
    const float* Xg = g_x + bt0*H;
    for(int i=tid;i<128*H;i+=128){
        int tl = i/H, c = i - tl*H;
        Xsm[tl*193 + c] = Xg[i];
    }
    __syncthreads();

    int tl = tid;
    long long g = bt0 + tl;
    int b = (int)(g >> 13);
    int t = (int)(g & (T-1));

    float p[NJ];
    #pragma unroll
    for(int j=0;j<NJ;j++) p[j] = proj_b[j];
    const float* xr = Xsm + tl*193;
    for(int c=0;c<H;c+=4){
        float x0=xr[c], x1=xr[c+1], x2=xr[c+2], x3=xr[c+3];
        #pragma unroll
        for(int j=0;j<NJ;j++){
            float4 wv = *(const float4*)(Wsm + j*H + c);
            p[j] += wv.x*x0 + wv.y*x1 + wv.z*x2 + wv.w*x3;
        }
    }
    float mask = xmask[(long long)b*T + t];
    #pragma unroll
    for(int j=0;j<NJ;j++) p[j] *= mask;

    const float inv_dn = 0.07216878364870323f;   // 1/sqrt(192)

    // widths
    float cwv[BINS+1], wsv[BINS];
    {
        float m = -1e30f;
        #pragma unroll
        for(int j=0;j<BINS;j++) m = fmaxf(m, p[j]);
        float e[BINS]; float ssum = 0.f;
        #pragma unroll
        for(int j=0;j<BINS;j++){ e[j] = expf((p[j]-m)*inv_dn); ssum += e[j]; }
        float inv = 1.0f/ssum;
        float cum = 0.f;
        cwv[0] = -TAILV;
        #pragma unroll
        for(int j=0;j<BINS;j++){
            float wj = 1e-3f + 0.99f*e[j]*inv;
            cum += wj;
            cwv[j+1] = 2.0f*TAILV*cum - TAILV;
        }
        cwv[BINS] = TAILV;
        #pragma unroll
        for(int j=0;j<BINS;j++) wsv[j] = cwv[j+1]-cwv[j];
    }
    // heights
    float chv[BINS+1], hsv[BINS];
    {
        float m = -1e30f;
        #pragma unroll
        for(int j=0;j<BINS;j++) m = fmaxf(m, p[BINS+j]);
        float e[BINS]; float ssum = 0.f;
        #pragma unroll
        for(int j=0;j<BINS;j++){ e[j] = expf((p[BINS+j]-m)*inv_dn); ssum += e[j]; }
        float inv = 1.0f/ssum;
        float cum = 0.f;
        chv[0] = -TAILV;
        #pragma unroll
        for(int j=0;j<BINS;j++){
            float hj = 1e-3f + 0.99f*e[j]*inv;
            cum += hj;
            chv[j+1] = 2.0f*TAILV*cum - TAILV;
        }
        chv[BINS] = TAILV;
        #pragma unroll
        for(int j=0;j<BINS;j++) hsv[j] = chv[j+1]-chv[j];
    }
    // derivatives (boundary pads give exactly 1.0: md + softplus(log(exp(1-md)-1)) = 1)
    float derv[BINS+1];
    derv[0] = 1.0f; derv[BINS] = 1.0f;
    #pragma unroll
    for(int k=1;k<BINS;k++){
        float u = p[2*BINS + k - 1];
        float sp = (u > 20.f) ? u : log1pf(expf(u));
        derv[k] = 1e-3f + sp;
    }

    float xbv = x[((long long)b*2+1)*T + t];
    bool inside = (xbv >= -TAILV) && (xbv <= TAILV);
    float xc = fminf(fmaxf(xbv, -TAILV), TAILV);
    int idx = 0;
    #pragma unroll
    for(int j=0;j<BINS;j++) idx += (xc >= cwv[j]) ? 1 : 0;
    idx -= 1;
    idx = max(0, min(BINS-1, idx));

    float icw = cwv[idx], ibw = wsv[idx];
    float ich = chv[idx], ih  = hsv[idx];
    float idl = ih/ibw;
    float dk  = derv[idx], dk1 = derv[idx+1];
    float th  = (xc - icw)/ibw;
    float t1m = th*(1.0f - th);
    float num = ih*(idl*th*th + dk*t1m);
    float den = idl + (dk + dk1 - 2.0f*idl)*t1m;
    float outv = ich + num/den;
    float omt = 1.0f - th;
    float dnum = idl*idl*(dk1*th*th + 2.0f*idl*t1m + dk*omt*omt);
    float lad = logf(dnum) - 2.0f*logf(den);

    float xb2 = inside ? outv : xbv;
    lad = inside ? lad : 0.0f;

    float xav = x[((long long)b*2)*T + t];
    out[(long long)b*2*T + t]     = xav*mask;
    out[(long long)b*2*T + T + t] = xb2*mask;

    float lv = lad*mask;
    #pragma unroll
    for(int o=16;o>0;o>>=1) lv += __shfl_xor_sync(0xffffffffu, lv, o);
    __shared__ float red[4];
    if((tid & 31) == 0) red[tid>>5] = lv;
    __syncthreads();
    if(tid == 0)
        atomicAdd(out + (long long)B*2*T + b, red[0]+red[1]+red[2]+red[3]);
}

// ---------------------------------------------------------------------------
extern "C" void kernel_launch(void* const* d_in, const int* in_sizes, int n_in,
                              void* d_out, int out_size)
{
    const float* x      = (const float*)d_in[0];
    const float* xmask  = (const float*)d_in[1];
    const float* in_w   = (const float*)d_in[2];
    const float* in_b   = (const float*)d_in[3];
    const float* dw_w   = (const float*)d_in[4];
    const float* dw_b   = (const float*)d_in[5];
    const float* ln1_g  = (const float*)d_in[6];
    const float* ln1_b  = (const float*)d_in[7];
    const float* pw_w   = (const float*)d_in[8];
    const float* pw_b   = (const float*)d_in[9];
    const float* ln2_g  = (const float*)d_in[10];
    const float* ln2_b  = (const float*)d_in[11];
    const float* proj_w = (const float*)d_in[12];
    const float* proj_b = (const float*)d_in[13];
    float* out = (float*)d_out;

    cudaFuncSetAttribute(k_gemm,   cudaFuncAttributeMaxDynamicSharedMemorySize, GEMM_SMEM_BYTES);
    cudaFuncSetAttribute(k_spline, cudaFuncAttributeMaxDynamicSharedMemorySize, SPLINE_SMEM_BYTES);

    k_init<<<(BT*H)/256, 256>>>(x, in_w, in_b);
    k_zero<<<1, 32>>>(out);
    int dil = 1;
    for(int L=0; L<3; L++){
        k_conv<<<BT/8, 256>>>(L, dil, xmask, dw_w, dw_b, ln1_g, ln1_b);
        k_gemm<<<BT/64, 256, GEMM_SMEM_BYTES>>>(L, pw_w, pw_b, ln2_g, ln2_b);
        dil *= 3;
    }
    k_spline<<<BT/128, 128, SPLINE_SMEM_BYTES>>>(x, xmask, proj_w, proj_b, out);
}

// round 3
// speedup vs baseline: 2.8778x; 2.8778x over previous
#include <cuda_runtime.h>
#include <cuda_bf16.h>
#include <math.h>
#include <stdint.h>

#define B 32
#define T 8192
#define H 192
#define BT (B*T)
#define BINS 10
#define TAILV 5.0f
#define NJ 29

// residual stream (f32) and conv output split to bf16 hi/lo, layout [b][t][c]
__device__ float g_x[(size_t)BT*H];
__device__ __align__(16) __nv_bfloat16 g_yh[(size_t)BT*H];
__device__ __align__(16) __nv_bfloat16 g_yl[(size_t)BT*H];
// padded weight image: [layer][hi/lo][o=192][pad 200] bf16
__device__ __align__(16) __nv_bfloat16 g_wp[3*2*192*200];

__device__ __forceinline__ float gelu_exact(float v){
    return 0.5f*v*(1.0f+erff(v*0.70710678118654752f));
}

__device__ __forceinline__ uint32_t smem_u32(const void* p){
    uint32_t a;
    asm("{ .reg .u64 t; cvta.to.shared.u64 t, %1; cvt.u32.u64 %0, t; }" : "=r"(a) : "l"(p));
    return a;
}

#define LDSM4(r, addr) \
    asm volatile("ldmatrix.sync.aligned.m8n8.x4.shared.b16 {%0,%1,%2,%3}, [%4];" \
        : "=r"((r)[0]),"=r"((r)[1]),"=r"((r)[2]),"=r"((r)[3]) : "r"(addr))

#define MMA16816(d, a, b0, b1) \
    asm volatile("mma.sync.aligned.m16n8k16.row.col.f32.bf16.bf16.f32 " \
        "{%0,%1,%2,%3},{%4,%5,%6,%7},{%8,%9},{%0,%1,%2,%3};" \
        : "+f"((d)[0]),"+f"((d)[1]),"+f"((d)[2]),"+f"((d)[3]) \
        : "r"((a)[0]),"r"((a)[1]),"r"((a)[2]),"r"((a)[3]), "r"(b0),"r"(b1))

#define CP16(dst, src) \
    asm volatile("cp.async.cg.shared.global [%0], [%1], 16;" :: "r"(dst), "l"(src))
#define CP_COMMIT asm volatile("cp.async.commit_group;" ::: "memory")
#define CP_WAIT1  asm volatile("cp.async.wait_group 1;" ::: "memory")
#define CP_WAIT0  asm volatile("cp.async.wait_group 0;" ::: "memory")

// ---------------------------------------------------------------------------
__global__ void k_init(const float* __restrict__ x,
                       const float* __restrict__ in_w,
                       const float* __restrict__ in_b)
{
    long long idx = (long long)blockIdx.x*256 + threadIdx.x;
    int c = (int)(idx % H);
    long long bt = idx / H;
    int b = (int)(bt >> 13);
    int t = (int)(bt & (T-1));
    float xa = x[((long long)b*2)*T + t];
    g_x[idx] = in_w[c]*xa + in_b[c];
}

__global__ void k_zero(float* __restrict__ out){
    out[(long long)B*2*T + threadIdx.x] = 0.0f;
}

// weight prep: fp32 -> bf16 hi/lo into padded image rows of 200
__global__ void k_prepw(const float* __restrict__ pw_w){
    int i = blockIdx.x*256 + threadIdx.x;
    if (i >= 3*H*H) return;
    int L = i / (H*H);
    int r = i - L*(H*H);
    int o = r / H, c = r - o*H;
    float w = pw_w[i];
    __nv_bfloat16 hb = __float2bfloat16(w);
    __nv_bfloat16 lb = __float2bfloat16(w - __bfloat162float(hb));
    g_wp[((size_t)(L*2+0)*192 + o)*200 + c] = hb;
    g_wp[((size_t)(L*2+1)*192 + o)*200 + c] = lb;
}

// ---------------------------------------------------------------------------
// depthwise dilated conv (K=3) + LN + exact gelu -> bf16 hi/lo. warp per t.
__global__ void __launch_bounds__(256) k_conv(int layer, int dil,
    const float* __restrict__ xmask,
    const float* __restrict__ dw_w, const float* __restrict__ dw_b,
    const float* __restrict__ ln_g, const float* __restrict__ ln_b)
{
    int wid = threadIdx.x >> 5, lane = threadIdx.x & 31;
    long long gidx = (long long)blockIdx.x*8 + wid;
    int b = (int)(gidx >> 13);
    int t = (int)(gidx & (T-1));
    const float* base = g_x + gidx*H;
    int tm = t - dil, tp = t + dil;
    bool hm = (tm >= 0), hp = (tp < T);
    float mm = hm ? xmask[(long long)b*T + tm] : 0.f;
    float m0 = xmask[(long long)b*T + t];
    float mp = hp ? xmask[(long long)b*T + tp] : 0.f;
    const float* bm = base - (long long)dil*H;
    const float* bp = base + (long long)dil*H;
    const float* wbase = dw_w + (long long)layer*H*3;
    const float* bbase = dw_b + layer*H;
    float v[6];
    float s = 0.f, sq = 0.f;
    #pragma unroll
    for(int j=0;j<6;j++){
        int c = lane + 32*j;
        float w0 = wbase[c*3+0], w1 = wbase[c*3+1], w2 = wbase[c*3+2];
        float a0 = hm ? bm[c]*mm : 0.f;
        float a1 = base[c]*m0;
        float a2 = hp ? bp[c]*mp : 0.f;
        float r = w0*a0 + w1*a1 + w2*a2 + bbase[c];
        v[j] = r; s += r; sq += r*r;
    }
    #pragma unroll
    for(int o=16;o>0;o>>=1){
        s  += __shfl_xor_sync(0xffffffffu, s,  o);
        sq += __shfl_xor_sync(0xffffffffu, sq, o);
    }
    float mu = s*(1.0f/H);
    float var = sq*(1.0f/H) - mu*mu;
    float rs = rsqrtf(var + 1e-5f);
    const float* gg = ln_g + layer*H;
    const float* gb = ln_b + layer*H;
    __nv_bfloat16* oh = g_yh + gidx*H;
    __nv_bfloat16* ol = g_yl + gidx*H;
    #pragma unroll
    for(int j=0;j<6;j++){
        int c = lane + 32*j;
        float yv = gelu_exact((v[j]-mu)*rs*gg[c] + gb[c]);
        __nv_bfloat16 hb = __float2bfloat16(yv);
        oh[c] = hb;
        ol[c] = __float2bfloat16(yv - __bfloat162float(hb));
    }
}

// ---------------------------------------------------------------------------
// warp-MMA GEMM: D[t(128), o(192)] = Y . W^T, split-bf16 (3 passes)
// + fused bias + LN(over o) + gelu + residual into g_x.
// smem: B image hi(0..76800) lo(76800..153600); A bufs 4x10240 at 153600;
//       params 576 f32 at 194560. Red arrays overlay A buf area.
#define BSM_HI   0
#define BSM_LO   76800
#define ABUF     153600
#define PAROFF   194560
#define GEMM_SMEM_BYTES (PAROFF + 2304)

__global__ void __launch_bounds__(256,1) k_gemm_mma(int layer,
    const float* __restrict__ pw_b,
    const float* __restrict__ ln_g, const float* __restrict__ ln_b)
{
    extern __shared__ char smem[];
    uint32_t sbase = smem_u32(smem);
    int tid = threadIdx.x;
    int wid = tid >> 5, lane = tid & 31;
    int wm = wid & 3, wn = wid >> 2;        // 4 warps in M, 2 in N
    int q = lane >> 2, qi = lane & 3;
    long long bt0 = (long long)blockIdx.x * 128;

    // copy padded weight image (hi+lo, 153600B) into smem
    {
        const uint4* src = (const uint4*)(g_wp + (size_t)layer*2*192*200);
        uint4* dst = (uint4*)smem;
        #pragma unroll 4
        for(int i=tid;i<9600;i+=256) dst[i] = src[i];
    }
    // params
    float* par = (float*)(smem + PAROFF);
    if(tid < 192){
        par[tid]       = pw_b[layer*H + tid];
        par[192 + tid] = ln_g[layer*H + tid];
        par[384 + tid] = ln_b[layer*H + tid];
    }

    // A chunk cp.async loaders: chunk = 32 k, 128 rows x 64B per dt
    // id = tid*2+j in 0..511: row = id>>2, seg = id&3 (16B segments)
    int id0 = tid*2;
    int rowL0 = id0>>2,   segL0 = id0&3;
    int rowL1 = (id0+1)>>2, segL1 = (id0+1)&3;
    uint32_t dstOff0 = (uint32_t)rowL0*80 + (uint32_t)segL0*16;
    uint32_t dstOff1 = (uint32_t)rowL1*80 + (uint32_t)segL1*16;
    const __nv_bfloat16* srcH0b = g_yh + (bt0+rowL0)*H + segL0*8;
    const __nv_bfloat16* srcH1b = g_yh + (bt0+rowL1)*H + segL1*8;
    const __nv_bfloat16* srcL0b = g_yl + (bt0+rowL0)*H + segL0*8;
    const __nv_bfloat16* srcL1b = g_yl + (bt0+rowL1)*H + segL1*8;

#define ISSUE_CHUNK(cc, buf) do { \
    uint32_t _ah = sbase + ABUF + (buf)*10240; \
    uint32_t _al = _ah + 20480; \
    int _k = (cc)*32; \
    CP16(_ah + dstOff0, srcH0b + _k); \
    CP16(_ah + dstOff1, srcH1b + _k); \
    CP16(_al + dstOff0, srcL0b + _k); \
    CP16(_al + dstOff1, srcL1b + _k); \
    CP_COMMIT; \
} while(0)

    ISSUE_CHUNK(0, 0);
    ISSUE_CHUNK(1, 1);

    // per-thread ldmatrix base offsets
    int g2 = lane >> 3, lr = lane & 7;
    uint32_t aOff[2];
    #pragma unroll
    for(int mt=0;mt<2;mt++)
        aOff[mt] = (uint32_t)(wm*32 + mt*16 + (g2&1)*8 + lr)*80 + (uint32_t)(g2>>1)*16;
    uint32_t bOff[6];
    #pragma unroll
    for(int i=0;i<6;i++)
        bOff[i] = (uint32_t)(wn*96 + i*16 + (g2>>1)*8 + lr)*400 + (uint32_t)(g2&1)*16;

    float acc[2][12][4];
    #pragma unroll
    for(int mt=0;mt<2;mt++)
        #pragma unroll
        for(int nt=0;nt<12;nt++)
            #pragma unroll
            for(int r=0;r<4;r++) acc[mt][nt][r] = 0.f;

    #pragma unroll 1
    for(int c=0;c<6;c++){
        if(c==5){ CP_WAIT0; } else { CP_WAIT1; }
        __syncthreads();
        uint32_t abufH = sbase + ABUF + (c&1)*10240;
        uint32_t abufL = abufH + 20480;
        #pragma unroll
        for(int ks=0;ks<2;ks++){
            uint32_t kA = ks*32;
            uint32_t kB = (uint32_t)c*64 + ks*32;
            uint32_t ah[2][4], al[2][4], bb[6][4];
            LDSM4(ah[0], abufH + aOff[0] + kA);
            LDSM4(ah[1], abufH + aOff[1] + kA);
            LDSM4(al[0], abufL + aOff[0] + kA);
            LDSM4(al[1], abufL + aOff[1] + kA);
            #pragma unroll
            for(int i=0;i<6;i++) LDSM4(bb[i], sbase + BSM_HI + bOff[i] + kB);
            // hi*hi and lo*hi
            #pragma unroll
            for(int mt=0;mt<2;mt++)
                #pragma unroll
                for(int i=0;i<6;i++){
                    MMA16816(acc[mt][2*i],   ah[mt], bb[i][0], bb[i][1]);
                    MMA16816(acc[mt][2*i+1], ah[mt], bb[i][2], bb[i][3]);
                    MMA16816(acc[mt][2*i],   al[mt], bb[i][0], bb[i][1]);
                    MMA16816(acc[mt][2*i+1], al[mt], bb[i][2], bb[i][3]);
                }
            // hi*lo
            #pragma unroll
            for(int i=0;i<6;i++) LDSM4(bb[i], sbase + BSM_LO + bOff[i] + kB);
            #pragma unroll
            for(int mt=0;mt<2;mt++)
                #pragma unroll
                for(int i=0;i<6;i++){
                    MMA16816(acc[mt][2*i],   ah[mt], bb[i][0], bb[i][1]);
                    MMA16816(acc[mt][2*i+1], ah[mt], bb[i][2], bb[i][3]);
                }
        }
        __syncthreads();
        if(c<4) ISSUE_CHUNK(c+2, c&1);
    }

    // ---------------- epilogue: bias + LN + gelu + residual ----------------
    float* red1 = (float*)(smem + ABUF);
    float* red2 = red1 + 256;
    float* musm = red1 + 512;
    float* rssm = red1 + 640;

    float s1[2][2] = {{0.f,0.f},{0.f,0.f}};
    float s2[2][2] = {{0.f,0.f},{0.f,0.f}};
    #pragma unroll
    for(int mt=0;mt<2;mt++)
        #pragma unroll
        for(int nt=0;nt<12;nt++){
            int col = wn*96 + nt*8 + qi*2;
            float b0 = par[col], b1 = par[col+1];
            acc[mt][nt][0] += b0; acc[mt][nt][1] += b1;
            acc[mt][nt][2] += b0; acc[mt][nt][3] += b1;
            #pragma unroll
            for(int h=0;h<2;h++){
                float v0 = acc[mt][nt][h*2], v1 = acc[mt][nt][h*2+1];
                s1[mt][h] += v0 + v1;
                s2[mt][h] += v0*v0 + v1*v1;
            }
        }
    #pragma unroll
    for(int mt=0;mt<2;mt++)
        #pragma unroll
        for(int h=0;h<2;h++){
            float a = s1[mt][h], b2 = s2[mt][h];
            a  += __shfl_xor_sync(0xffffffffu, a, 1);
            a  += __shfl_xor_sync(0xffffffffu, a, 2);
            b2 += __shfl_xor_sync(0xffffffffu, b2, 1);
            b2 += __shfl_xor_sync(0xffffffffu, b2, 2);
            if(qi==0){
                int row = wm*32 + mt*16 + h*8 + q;
                red1[wn*128 + row] = a;
                red2[wn*128 + row] = b2;
            }
        }
    __syncthreads();
    if(tid < 128){
        float t1 = red1[tid] + red1[128+tid];
        float t2 = red2[tid] + red2[128+tid];
        float mu = t1*(1.0f/H);
        musm[tid] = mu;
        rssm[tid] = rsqrtf(t2*(1.0f/H) - mu*mu + 1e-5f);
    }
    __syncthreads();

    const float* lg = par + 192;
    const float* lb = par + 384;
    #pragma unroll
    for(int mt=0;mt<2;mt++)
        #pragma unroll
        for(int h=0;h<2;h++){
            int row = wm*32 + mt*16 + h*8 + q;
            float mu = musm[row], rs = rssm[row];
            float* xrow = g_x + (bt0+row)*H;
            #pragma unroll
            for(int nt=0;nt<12;nt++){
                int col = wn*96 + nt*8 + qi*2;
                float v0 = acc[mt][nt][h*2], v1 = acc[mt][nt][h*2+1];
                float2 res = *(float2*)(xrow + col);
                float o0 = gelu_exact((v0-mu)*rs*lg[col]   + lb[col])   + res.x;
                float o1 = gelu_exact((v1-mu)*rs*lg[col+1] + lb[col+1]) + res.y;
                *(float2*)(xrow + col) = make_float2(o0, o1);
            }
        }
}

// ---------------------------------------------------------------------------
// proj (192->29) + rational-quadratic spline + outputs + logdet
#define SPLINE_SMEM_FLOATS (NJ*H + 128*193)
#define SPLINE_SMEM_BYTES  (SPLINE_SMEM_FLOATS*4)

__global__ void __launch_bounds__(128) k_spline(
    const float* __restrict__ x, const float* __restrict__ xmask,
    const float* __restrict__ proj_w, const float* __restrict__ proj_b,
    float* __restrict__ out)
{
    extern __shared__ float sm[];
    float* Wsm = sm;
    float* Xsm = sm + NJ*H;
    int tid = threadIdx.x;
    long long bt0 = (long long)blockIdx.x*128;

    for(int i=tid;i<NJ*H;i+=128) Wsm[i] = proj_w[i];
    const float* Xg = g_x + bt0*H;
    for(int i=tid;i<128*H;i+=128){
        int tl = i/H, c = i - tl*H;
        Xsm[tl*193 + c] = Xg[i];
    }
    __syncthreads();

    int tl = tid;
    long long g = bt0 + tl;
    int b = (int)(g >> 13);
    int t = (int)(g & (T-1));

    float p[NJ];
    #pragma unroll
    for(int j=0;j<NJ;j++) p[j] = proj_b[j];
    const float* xr = Xsm + tl*193;
    for(int c=0;c<H;c+=4){
        float x0=xr[c], x1=xr[c+1], x2=xr[c+2], x3=xr[c+3];
        #pragma unroll
        for(int j=0;j<NJ;j++){
            float4 wv = *(const float4*)(Wsm + j*H + c);
            p[j] += wv.x*x0 + wv.y*x1 + wv.z*x2 + wv.w*x3;
        }
    }
    float mask = xmask[(long long)b*T + t];
    #pragma unroll
    for(int j=0;j<NJ;j++) p[j] *= mask;

    const float inv_dn = 0.07216878364870323f;

    float cwv[BINS+1], wsv[BINS];
    {
        float m = -1e30f;
        #pragma unroll
        for(int j=0;j<BINS;j++) m = fmaxf(m, p[j]);
        float e[BINS]; float ssum = 0.f;
        #pragma unroll
        for(int j=0;j<BINS;j++){ e[j] = expf((p[j]-m)*inv_dn); ssum += e[j]; }
        float inv = 1.0f/ssum;
        float cum = 0.f;
        cwv[0] = -TAILV;
        #pragma unroll
        for(int j=0;j<BINS;j++){
            float wj = 1e-3f + 0.99f*e[j]*inv;
            cum += wj;
            cwv[j+1] = 2.0f*TAILV*cum - TAILV;
        }
        cwv[BINS] = TAILV;
        #pragma unroll
        for(int j=0;j<BINS;j++) wsv[j] = cwv[j+1]-cwv[j];
    }
    float chv[BINS+1], hsv[BINS];
    {
        float m = -1e30f;
        #pragma unroll
        for(int j=0;j<BINS;j++) m = fmaxf(m, p[BINS+j]);
        float e[BINS]; float ssum = 0.f;
        #pragma unroll
        for(int j=0;j<BINS;j++){ e[j] = expf((p[BINS+j]-m)*inv_dn); ssum += e[j]; }
        float inv = 1.0f/ssum;
        float cum = 0.f;
        chv[0] = -TAILV;
        #pragma unroll
        for(int j=0;j<BINS;j++){
            float hj = 1e-3f + 0.99f*e[j]*inv;
            cum += hj;
            chv[j+1] = 2.0f*TAILV*cum - TAILV;
        }
        chv[BINS] = TAILV;
        #pragma unroll
        for(int j=0;j<BINS;j++) hsv[j] = chv[j+1]-chv[j];
    }
    float derv[BINS+1];
    derv[0] = 1.0f; derv[BINS] = 1.0f;
    #pragma unroll
    for(int k=1;k<BINS;k++){
        float u = p[2*BINS + k - 1];
        float sp = (u > 20.f) ? u : log1pf(expf(u));
        derv[k] = 1e-3f + sp;
    }

    float xbv = x[((long long)b*2+1)*T + t];
    bool inside = (xbv >= -TAILV) && (xbv <= TAILV);
    float xc = fminf(fmaxf(xbv, -TAILV), TAILV);
    int idx = 0;
    #pragma unroll
    for(int j=0;j<BINS;j++) idx += (xc >= cwv[j]) ? 1 : 0;
    idx -= 1;
    idx = max(0, min(BINS-1, idx));

    float icw = cwv[idx], ibw = wsv[idx];
    float ich = chv[idx], ih  = hsv[idx];
    float idl = ih/ibw;
    float dk  = derv[idx], dk1 = derv[idx+1];
    float th  = (xc - icw)/ibw;
    float t1m = th*(1.0f - th);
    float num = ih*(idl*th*th + dk*t1m);
    float den = idl + (dk + dk1 - 2.0f*idl)*t1m;
    float outv = ich + num/den;
    float omt = 1.0f - th;
    float dnum = idl*idl*(dk1*th*th + 2.0f*idl*t1m + dk*omt*omt);
    float lad = logf(dnum) - 2.0f*logf(den);

    float xb2 = inside ? outv : xbv;
    lad = inside ? lad : 0.0f;

    float xav = x[((long long)b*2)*T + t];
    out[(long long)b*2*T + t]     = xav*mask;
    out[(long long)b*2*T + T + t] = xb2*mask;

    float lv = lad*mask;
    #pragma unroll
    for(int o=16;o>0;o>>=1) lv += __shfl_xor_sync(0xffffffffu, lv, o);
    __shared__ float red[4];
    if((tid & 31) == 0) red[tid>>5] = lv;
    __syncthreads();
    if(tid == 0)
        atomicAdd(out + (long long)B*2*T + b, red[0]+red[1]+red[2]+red[3]);
}

// ---------------------------------------------------------------------------
extern "C" void kernel_launch(void* const* d_in, const int* in_sizes, int n_in,
                              void* d_out, int out_size)
{
    const float* x      = (const float*)d_in[0];
    const float* xmask  = (const float*)d_in[1];
    const float* in_w   = (const float*)d_in[2];
    const float* in_b   = (const float*)d_in[3];
    const float* dw_w   = (const float*)d_in[4];
    const float* dw_b   = (const float*)d_in[5];
    const float* ln1_g  = (const float*)d_in[6];
    const float* ln1_b  = (const float*)d_in[7];
    const float* pw_w   = (const float*)d_in[8];
    const float* pw_b   = (const float*)d_in[9];
    const float* ln2_g  = (const float*)d_in[10];
    const float* ln2_b  = (const float*)d_in[11];
    const float* proj_w = (const float*)d_in[12];
    const float* proj_b = (const float*)d_in[13];
    float* out = (float*)d_out;

    cudaFuncSetAttribute(k_gemm_mma, cudaFuncAttributeMaxDynamicSharedMemorySize, GEMM_SMEM_BYTES);
    cudaFuncSetAttribute(k_spline,   cudaFuncAttributeMaxDynamicSharedMemorySize, SPLINE_SMEM_BYTES);

    k_prepw<<<(3*H*H + 255)/256, 256>>>(pw_w);
    k_init<<<(BT*H)/256, 256>>>(x, in_w, in_b);
    k_zero<<<1, 32>>>(out);
    int dil = 1;
    for(int L=0; L<3; L++){
        k_conv<<<BT/8, 256>>>(L, dil, xmask, dw_w, dw_b, ln1_g, ln1_b);
        k_gemm_mma<<<BT/128, 256, GEMM_SMEM_BYTES>>>(L, pw_b, ln2_g, ln2_b);
        dil *= 3;
    }
    k_spline<<<BT/128, 128, SPLINE_SMEM_BYTES>>>(x, xmask, proj_w, proj_b, out);
}

// round 4
// speedup vs baseline: 3.4835x; 1.2105x over previous
#include <cuda_runtime.h>
#include <cuda_bf16.h>
#include <math.h>
#include <stdint.h>

#define B 32
#define T 8192
#define H 192
#define BT (B*T)
#define BINS 10
#define TAILV 5.0f
#define NJ 29

// residual stream (f32) and bf16 hi/lo stream, layout [b][t][c]
__device__ float g_x[(size_t)BT*H];
__device__ __align__(16) __nv_bfloat16 g_yh[(size_t)BT*H];
__device__ __align__(16) __nv_bfloat16 g_yl[(size_t)BT*H];
// padded pw weight image: [layer][hi/lo][o=192][pad 200] bf16
__device__ __align__(16) __nv_bfloat16 g_wp[3*2*192*200];
// padded proj weight image: [hi/lo][32][pad 200] bf16
__device__ __align__(16) __nv_bfloat16 g_pw[2*32*200];
// transposed depthwise weights: [layer][tap][c]
__device__ float g_dwt[3*3*192];

__device__ __forceinline__ float gelu_exact(float v){
    return 0.5f*v*(1.0f+erff(v*0.70710678118654752f));
}

__device__ __forceinline__ uint32_t smem_u32(const void* p){
    uint32_t a;
    asm("{ .reg .u64 t; cvta.to.shared.u64 t, %1; cvt.u32.u64 %0, t; }" : "=r"(a) : "l"(p));
    return a;
}

#define LDSM4(r, addr) \
    asm volatile("ldmatrix.sync.aligned.m8n8.x4.shared.b16 {%0,%1,%2,%3}, [%4];" \
        : "=r"((r)[0]),"=r"((r)[1]),"=r"((r)[2]),"=r"((r)[3]) : "r"(addr))

#define MMA16816(d, a, b0, b1) \
    asm volatile("mma.sync.aligned.m16n8k16.row.col.f32.bf16.bf16.f32 " \
        "{%0,%1,%2,%3},{%4,%5,%6,%7},{%8,%9},{%0,%1,%2,%3};" \
        : "+f"((d)[0]),"+f"((d)[1]),"+f"((d)[2]),"+f"((d)[3]) \
        : "r"((a)[0]),"r"((a)[1]),"r"((a)[2]),"r"((a)[3]), "r"(b0),"r"(b1))

#define CP16(dst, src) \
    asm volatile("cp.async.cg.shared.global [%0], [%1], 16;" :: "r"(dst), "l"(src))
#define CP_COMMIT asm volatile("cp.async.commit_group;" ::: "memory")
#define CP_WAIT2  asm volatile("cp.async.wait_group 2;" ::: "memory")
#define CP_WAIT1  asm volatile("cp.async.wait_group 1;" ::: "memory")
#define CP_WAIT0  asm volatile("cp.async.wait_group 0;" ::: "memory")

// ---------------------------------------------------------------------------
// prep: pw split image, proj split image, dw transpose, zero logdet
__global__ void k_prep(const float* __restrict__ pw_w,
                       const float* __restrict__ proj_w,
                       const float* __restrict__ dw_w,
                       float* __restrict__ out)
{
    int i = blockIdx.x*256 + threadIdx.x;
    if (i < 3*H*H){
        int L = i / (H*H);
        int r = i - L*(H*H);
        int o = r / H, c = r - o*H;
        float w = pw_w[i];
        __nv_bfloat16 hb = __float2bfloat16(w);
        __nv_bfloat16 lb = __float2bfloat16(w - __bfloat162float(hb));
        g_wp[((size_t)(L*2+0)*192 + o)*200 + c] = hb;
        g_wp[((size_t)(L*2+1)*192 + o)*200 + c] = lb;
    }
    if (i < 2*32*200){
        int p = i / 6400;
        int rem = i - p*6400;
        int r = rem / 200, c = rem - r*200;
        float w = (r < NJ && c < H) ? proj_w[r*H + c] : 0.0f;
        __nv_bfloat16 hb = __float2bfloat16(w);
        __nv_bfloat16 lb = __float2bfloat16(w - __bfloat162float(hb));
        g_pw[i] = p ? lb : hb;
    }
    if (i < 3*3*H){
        int L = i / (3*H);
        int rem = i - L*(3*H);
        int c = rem / 3, k = rem - c*3;
        g_dwt[L*(3*H) + k*H + c] = dw_w[i];
    }
    if (i < B) out[(long long)B*2*T + i] = 0.0f;
}

// ---------------------------------------------------------------------------
__global__ void k_init(const float* __restrict__ x,
                       const float* __restrict__ in_w,
                       const float* __restrict__ in_b)
{
    long long idx = (long long)blockIdx.x*256 + threadIdx.x;
    int c = (int)(idx % H);
    long long bt = idx / H;
    int b = (int)(bt >> 13);
    int t = (int)(bt & (T-1));
    float xa = x[((long long)b*2)*T + t];
    g_x[idx] = in_w[c]*xa + in_b[c];
}

// ---------------------------------------------------------------------------
// depthwise dilated conv (K=3) + LN + exact gelu -> bf16 hi/lo.
// warp handles 4 consecutive t; lane owns 6 contiguous channels.
__global__ void __launch_bounds__(256) k_conv(int layer, int dil,
    const float* __restrict__ xmask,
    const float* __restrict__ dw_b,
    const float* __restrict__ ln_g, const float* __restrict__ ln_b)
{
    int wid = threadIdx.x >> 5, lane = threadIdx.x & 31;
    long long g0 = (long long)blockIdx.x*32 + wid*4;
    int b = (int)(g0 >> 13);
    int t0 = (int)(g0 & (T-1));
    int c0 = lane*6;

    // params (once per warp-tile)
    float w0[6], w1[6], w2[6], bbv[6], ggv[6], gbv[6];
    {
        const float* wt = g_dwt + layer*(3*H);
        #pragma unroll
        for(int p=0;p<3;p++){
            float2 a = *(const float2*)(wt + c0 + p*2);
            w0[p*2]=a.x; w0[p*2+1]=a.y;
            float2 bq = *(const float2*)(wt + H + c0 + p*2);
            w1[p*2]=bq.x; w1[p*2+1]=bq.y;
            float2 cq = *(const float2*)(wt + 2*H + c0 + p*2);
            w2[p*2]=cq.x; w2[p*2+1]=cq.y;
            float2 d = *(const float2*)(dw_b + layer*H + c0 + p*2);
            bbv[p*2]=d.x; bbv[p*2+1]=d.y;
            float2 e = *(const float2*)(ln_g + layer*H + c0 + p*2);
            ggv[p*2]=e.x; ggv[p*2+1]=e.y;
            float2 f = *(const float2*)(ln_b + layer*H + c0 + p*2);
            gbv[p*2]=f.x; gbv[p*2+1]=f.y;
        }
    }
    const float* mrow = xmask + (long long)b*T;

    #pragma unroll
    for(int tt=0;tt<4;tt++){
        long long row = g0 + tt;
        int t = t0 + tt;
        const float* base = g_x + row*H + c0;
        int tm = t - dil, tp = t + dil;
        bool hm = (tm >= 0), hp = (tp < T);
        float mm = hm ? mrow[tm] : 0.f;
        float m0 = mrow[t];
        float mp = hp ? mrow[tp] : 0.f;

        float xm[6], xz[6], xp[6];
        #pragma unroll
        for(int p=0;p<3;p++){
            float2 a = *(const float2*)(base + p*2);
            xz[p*2]=a.x; xz[p*2+1]=a.y;
        }
        if(hm){
            const float* bmp = base - (long long)dil*H;
            #pragma unroll
            for(int p=0;p<3;p++){
                float2 a = *(const float2*)(bmp + p*2);
                xm[p*2]=a.x; xm[p*2+1]=a.y;
            }
        } else {
            #pragma unroll
            for(int k=0;k<6;k++) xm[k]=0.f;
        }
        if(hp){
            const float* bpp = base + (long long)dil*H;
            #pragma unroll
            for(int p=0;p<3;p++){
                float2 a = *(const float2*)(bpp + p*2);
                xp[p*2]=a.x; xp[p*2+1]=a.y;
            }
        } else {
            #pragma unroll
            for(int k=0;k<6;k++) xp[k]=0.f;
        }

        float v[6];
        float s=0.f, sq=0.f;
        #pragma unroll
        for(int k=0;k<6;k++){
            float r = w0[k]*(xm[k]*mm) + w1[k]*(xz[k]*m0) + w2[k]*(xp[k]*mp) + bbv[k];
            v[k]=r; s+=r; sq+=r*r;
        }
        #pragma unroll
        for(int o=16;o>0;o>>=1){
            s  += __shfl_xor_sync(0xffffffffu, s,  o);
            sq += __shfl_xor_sync(0xffffffffu, sq, o);
        }
        float mu = s*(1.0f/H);
        float rs = rsqrtf(sq*(1.0f/H) - mu*mu + 1e-5f);

        uint32_t hw[3], lw[3];
        #pragma unroll
        for(int p=0;p<3;p++){
            float y0 = gelu_exact((v[p*2]  -mu)*rs*ggv[p*2]   + gbv[p*2]);
            float y1 = gelu_exact((v[p*2+1]-mu)*rs*ggv[p*2+1] + gbv[p*2+1]);
            __nv_bfloat16 h0 = __float2bfloat16(y0);
            __nv_bfloat16 h1 = __float2bfloat16(y1);
            __nv_bfloat16 l0 = __float2bfloat16(y0 - __bfloat162float(h0));
            __nv_bfloat16 l1 = __float2bfloat16(y1 - __bfloat162float(h1));
            __nv_bfloat162 ph = __halves2bfloat162(h0,h1);
            __nv_bfloat162 pl = __halves2bfloat162(l0,l1);
            hw[p] = *(uint32_t*)&ph;
            lw[p] = *(uint32_t*)&pl;
        }
        uint32_t* oh = (uint32_t*)(g_yh + row*H + c0);
        uint32_t* ol = (uint32_t*)(g_yl + row*H + c0);
        oh[0]=hw[0]; oh[1]=hw[1]; oh[2]=hw[2];
        ol[0]=lw[0]; ol[1]=lw[1]; ol[2]=lw[2];
    }
}

// ---------------------------------------------------------------------------
// warp-MMA GEMM: D[t(128), o(192)] = Y . W^T, split-bf16 (3 passes)
// + fused bias + LN(over o) + gelu + residual into g_x.
#define BSM_HI   0
#define BSM_LO   76800
#define ABUF     153600
#define PAROFF   (ABUF + 3*20480)
#define GEMM_SMEM_BYTES (PAROFF + 2304)

__global__ void __launch_bounds__(256,1) k_gemm_mma(int layer, int last,
    const float* __restrict__ pw_b,
    const float* __restrict__ ln_g, const float* __restrict__ ln_b)
{
    extern __shared__ char smem[];
    uint32_t sbase = smem_u32(smem);
    int tid = threadIdx.x;
    int wid = tid >> 5, lane = tid & 31;
    int wm = wid & 3, wn = wid >> 2;        // 4 warps in M, 2 in N
    int q = lane >> 2, qi = lane & 3;
    long long bt0 = (long long)blockIdx.x * 128;

    // weight image (hi+lo, 153600B) into smem
    {
        const uint4* src = (const uint4*)(g_wp + (size_t)layer*2*192*200);
        uint4* dst = (uint4*)smem;
        #pragma unroll 4
        for(int i=tid;i<9600;i+=256) dst[i] = src[i];
    }
    float* par = (float*)(smem + PAROFF);
    if(tid < 192){
        par[tid]       = pw_b[layer*H + tid];
        par[192 + tid] = ln_g[layer*H + tid];
        par[384 + tid] = ln_b[layer*H + tid];
    }

    // A loaders: chunk = 32 k; id in 0..511: row=id>>2, seg=id&3
    int id0 = tid*2;
    int rowL0 = id0>>2,     segL0 = id0&3;
    int rowL1 = (id0+1)>>2, segL1 = (id0+1)&3;
    uint32_t dstOff0 = (uint32_t)rowL0*80 + (uint32_t)segL0*16;
    uint32_t dstOff1 = (uint32_t)rowL1*80 + (uint32_t)segL1*16;
    const __nv_bfloat16* srcH0b = g_yh + (bt0+rowL0)*H + segL0*8;
    const __nv_bfloat16* srcH1b = g_yh + (bt0+rowL1)*H + segL1*8;
    const __nv_bfloat16* srcL0b = g_yl + (bt0+rowL0)*H + segL0*8;
    const __nv_bfloat16* srcL1b = g_yl + (bt0+rowL1)*H + segL1*8;

#define ISSUE_CHUNK(cc, st) do { \
    uint32_t _ah = sbase + ABUF + (st)*20480; \
    uint32_t _al = _ah + 10240; \
    int _k = (cc)*32; \
    CP16(_ah + dstOff0, srcH0b + _k); \
    CP16(_ah + dstOff1, srcH1b + _k); \
    CP16(_al + dstOff0, srcL0b + _k); \
    CP16(_al + dstOff1, srcL1b + _k); \
    CP_COMMIT; \
} while(0)

    ISSUE_CHUNK(0, 0);
    ISSUE_CHUNK(1, 1);
    ISSUE_CHUNK(2, 2);

    int g2 = lane >> 3, lr = lane & 7;
    uint32_t aOff[2];
    #pragma unroll
    for(int mt=0;mt<2;mt++)
        aOff[mt] = (uint32_t)(wm*32 + mt*16 + (g2&1)*8 + lr)*80 + (uint32_t)(g2>>1)*16;
    uint32_t bOff[6];
    #pragma unroll
    for(int i=0;i<6;i++)
        bOff[i] = (uint32_t)(wn*96 + i*16 + (g2>>1)*8 + lr)*400 + (uint32_t)(g2&1)*16;

    float acc[2][12][4];
    #pragma unroll
    for(int mt=0;mt<2;mt++)
        #pragma unroll
        for(int nt=0;nt<12;nt++)
            #pragma unroll
            for(int r=0;r<4;r++) acc[mt][nt][r] = 0.f;

    #pragma unroll 1
    for(int c=0;c<6;c++){
        if(c<4){ CP_WAIT2; } else if(c==4){ CP_WAIT1; } else { CP_WAIT0; }
        __syncthreads();
        int st = c % 3;
        uint32_t abufH = sbase + ABUF + st*20480;
        uint32_t abufL = abufH + 10240;
        #pragma unroll
        for(int ks=0;ks<2;ks++){
            uint32_t kA = ks*32;
            uint32_t kB = (uint32_t)c*64 + ks*32;
            uint32_t ah[2][4], al[2][4], bb[6][4];
            LDSM4(ah[0], abufH + aOff[0] + kA);
            LDSM4(ah[1], abufH + aOff[1] + kA);
            LDSM4(al[0], abufL + aOff[0] + kA);
            LDSM4(al[1], abufL + aOff[1] + kA);
            #pragma unroll
            for(int i=0;i<6;i++) LDSM4(bb[i], sbase + BSM_HI + bOff[i] + kB);
            #pragma unroll
            for(int mt=0;mt<2;mt++)
                #pragma unroll
                for(int i=0;i<6;i++){
                    MMA16816(acc[mt][2*i],   ah[mt], bb[i][0], bb[i][1]);
                    MMA16816(acc[mt][2*i+1], ah[mt], bb[i][2], bb[i][3]);
                    MMA16816(acc[mt][2*i],   al[mt], bb[i][0], bb[i][1]);
                    MMA16816(acc[mt][2*i+1], al[mt], bb[i][2], bb[i][3]);
                }
            #pragma unroll
            for(int i=0;i<6;i++) LDSM4(bb[i], sbase + BSM_LO + bOff[i] + kB);
            #pragma unroll
            for(int mt=0;mt<2;mt++)
                #pragma unroll
                for(int i=0;i<6;i++){
                    MMA16816(acc[mt][2*i],   ah[mt], bb[i][0], bb[i][1]);
                    MMA16816(acc[mt][2*i+1], ah[mt], bb[i][2], bb[i][3]);
                }
        }
        __syncthreads();
        if(c<3) ISSUE_CHUNK(c+3, st);
    }

    // ---------------- epilogue: bias + LN + gelu + residual ----------------
    float* red1 = (float*)(smem + ABUF);
    float* red2 = red1 + 256;
    float* musm = red1 + 512;
    float* rssm = red1 + 640;

    float s1[2][2] = {{0.f,0.f},{0.f,0.f}};
    float s2[2][2] = {{0.f,0.f},{0.f,0.f}};
    #pragma unroll
    for(int mt=0;mt<2;mt++)
        #pragma unroll
        for(int nt=0;nt<12;nt++){
            int col = wn*96 + nt*8 + qi*2;
            float b0 = par[col], b1 = par[col+1];
            acc[mt][nt][0] += b0; acc[mt][nt][1] += b1;
            acc[mt][nt][2] += b0; acc[mt][nt][3] += b1;
            #pragma unroll
            for(int h=0;h<2;h++){
                float v0 = acc[mt][nt][h*2], v1 = acc[mt][nt][h*2+1];
                s1[mt][h] += v0 + v1;
                s2[mt][h] += v0*v0 + v1*v1;
            }
        }
    #pragma unroll
    for(int mt=0;mt<2;mt++)
        #pragma unroll
        for(int h=0;h<2;h++){
            float a = s1[mt][h], b2 = s2[mt][h];
            a  += __shfl_xor_sync(0xffffffffu, a, 1);
            a  += __shfl_xor_sync(0xffffffffu, a, 2);
            b2 += __shfl_xor_sync(0xffffffffu, b2, 1);
            b2 += __shfl_xor_sync(0xffffffffu, b2, 2);
            if(qi==0){
                int row = wm*32 + mt*16 + h*8 + q;
                red1[wn*128 + row] = a;
                red2[wn*128 + row] = b2;
            }
        }
    __syncthreads();
    if(tid < 128){
        float t1 = red1[tid] + red1[128+tid];
        float t2 = red2[tid] + red2[128+tid];
        float mu = t1*(1.0f/H);
        musm[tid] = mu;
        rssm[tid] = rsqrtf(t2*(1.0f/H) - mu*mu + 1e-5f);
    }
    __syncthreads();

    const float* lg = par + 192;
    const float* lb = par + 384;
    #pragma unroll
    for(int mt=0;mt<2;mt++)
        #pragma unroll
        for(int h=0;h<2;h++){
            int row = wm*32 + mt*16 + h*8 + q;
            float mu = musm[row], rs = rssm[row];
            float* xrow = g_x + (bt0+row)*H;
            __nv_bfloat16* yh = g_yh + (bt0+row)*H;
            __nv_bfloat16* yl = g_yl + (bt0+row)*H;
            #pragma unroll
            for(int nt=0;nt<12;nt++){
                int col = wn*96 + nt*8 + qi*2;
                float v0 = acc[mt][nt][h*2], v1 = acc[mt][nt][h*2+1];
                float2 res = *(float2*)(xrow + col);
                float o0 = gelu_exact((v0-mu)*rs*lg[col]   + lb[col])   + res.x;
                float o1 = gelu_exact((v1-mu)*rs*lg[col+1] + lb[col+1]) + res.y;
                *(float2*)(xrow + col) = make_float2(o0, o1);
                if(last){
                    __nv_bfloat16 h0 = __float2bfloat16(o0);
                    __nv_bfloat16 h1 = __float2bfloat16(o1);
                    __nv_bfloat16 l0 = __float2bfloat16(o0 - __bfloat162float(h0));
                    __nv_bfloat16 l1 = __float2bfloat16(o1 - __bfloat162float(h1));
                    __nv_bfloat162 ph = __halves2bfloat162(h0,h1);
                    __nv_bfloat162 pl = __halves2bfloat162(l0,l1);
                    *(__nv_bfloat162*)(yh + col) = ph;
                    *(__nv_bfloat162*)(yl + col) = pl;
                }
            }
        }
}

// ---------------------------------------------------------------------------
// spline: P = x_final . proj_w^T via split-bf16 mma, then RQ spline + logdet
// M=256 rows/CTA, 256 threads, 8 warps (each warp 32 rows, full N=32)
#define SP_PWHI 0
#define SP_PWLO 12800
#define SP_ABUF 25600
#define SP_P    25600
#define SPLINE_SMEM_BYTES (25600 + 2*40960)

__global__ void __launch_bounds__(256) k_spline(
    const float* __restrict__ x, const float* __restrict__ xmask,
    const float* __restrict__ proj_b,
    float* __restrict__ out)
{
    extern __shared__ char smem[];
    uint32_t sbase = smem_u32(smem);
    int tid = threadIdx.x;
    int wid = tid >> 5, lane = tid & 31;
    int q = lane >> 2, qi = lane & 3;
    long long bt0 = (long long)blockIdx.x * 256;

    // proj weight image 25600B
    {
        const uint4* src = (const uint4*)g_pw;
        uint4* dst = (uint4*)smem;
        #pragma unroll
        for(int i=tid;i<1600;i+=256) dst[i] = src[i];
    }

    // A loaders: 256 rows x 4 segs = 1024 ids; thread does 4 per buffer
    int rows[4], segs[4];
    #pragma unroll
    for(int m=0;m<4;m++){
        int id = tid + m*256;
        rows[m] = id >> 2; segs[m] = id & 3;
    }

#define SP_ISSUE(cc, st) do { \
    uint32_t _ah = sbase + SP_ABUF + (st)*40960; \
    uint32_t _al = _ah + 20480; \
    int _k = (cc)*32; \
    _Pragma("unroll") \
    for(int m=0;m<4;m++){ \
        uint32_t d = (uint32_t)rows[m]*80 + (uint32_t)segs[m]*16; \
        CP16(_ah + d, g_yh + (bt0+rows[m])*H + segs[m]*8 + _k); \
        CP16(_al + d, g_yl + (bt0+rows[m])*H + segs[m]*8 + _k); \
    } \
    CP_COMMIT; \
} while(0)

    SP_ISSUE(0, 0);
    SP_ISSUE(1, 1);

    int g2 = lane >> 3, lr = lane & 7;
    uint32_t aOff[2];
    #pragma unroll
    for(int mt=0;mt<2;mt++)
        aOff[mt] = (uint32_t)(wid*32 + mt*16 + (g2&1)*8 + lr)*80 + (uint32_t)(g2>>1)*16;
    uint32_t bOff[2];
    #pragma unroll
    for(int i=0;i<2;i++)
        bOff[i] = (uint32_t)(i*16 + (g2>>1)*8 + lr)*400 + (uint32_t)(g2&1)*16;

    float acc[2][4][4];
    #pragma unroll
    for(int mt=0;mt<2;mt++)
        #pragma unroll
        for(int nt=0;nt<4;nt++)
            #pragma unroll
            for(int r=0;r<4;r++) acc[mt][nt][r]=0.f;

    #pragma unroll 1
    for(int c=0;c<6;c++){
        if(c<5){ CP_WAIT1; } else { CP_WAIT0; }
        __syncthreads();
        uint32_t abufH = sbase + SP_ABUF + (c&1)*40960;
        uint32_t abufL = abufH + 20480;
        #pragma unroll
        for(int ks=0;ks<2;ks++){
            uint32_t kA = ks*32;
            uint32_t kB = (uint32_t)c*64 + ks*32;
            uint32_t ah[2][4], al[2][4], bb[2][4];
            LDSM4(ah[0], abufH + aOff[0] + kA);
            LDSM4(ah[1], abufH + aOff[1] + kA);
            LDSM4(al[0], abufL + aOff[0] + kA);
            LDSM4(al[1], abufL + aOff[1] + kA);
            LDSM4(bb[0], sbase + SP_PWHI + bOff[0] + kB);
            LDSM4(bb[1], sbase + SP_PWHI + bOff[1] + kB);
            #pragma unroll
            for(int mt=0;mt<2;mt++)
                #pragma unroll
                for(int i=0;i<2;i++){
                    MMA16816(acc[mt][2*i],   ah[mt], bb[i][0], bb[i][1]);
                    MMA16816(acc[mt][2*i+1], ah[mt], bb[i][2], bb[i][3]);
                    MMA16816(acc[mt][2*i],   al[mt], bb[i][0], bb[i][1]);
                    MMA16816(acc[mt][2*i+1], al[mt], bb[i][2], bb[i][3]);
                }
            LDSM4(bb[0], sbase + SP_PWLO + bOff[0] + kB);
            LDSM4(bb[1], sbase + SP_PWLO + bOff[1] + kB);
            #pragma unroll
            for(int mt=0;mt<2;mt++)
                #pragma unroll
                for(int i=0;i<2;i++){
                    MMA16816(acc[mt][2*i],   ah[mt], bb[i][0], bb[i][1]);
                    MMA16816(acc[mt][2*i+1], ah[mt], bb[i][2], bb[i][3]);
                }
        }
        __syncthreads();
        if(c<4) SP_ISSUE(c+2, c&1);
    }

    // write P to smem
    float* Psm = (float*)(smem + SP_P);
    #pragma unroll
    for(int mt=0;mt<2;mt++)
        #pragma unroll
        for(int h=0;h<2;h++){
            int row = wid*32 + mt*16 + h*8 + q;
            #pragma unroll
            for(int nt=0;nt<4;nt++){
                int col = nt*8 + qi*2;
                Psm[row*33 + col]   = acc[mt][nt][h*2];
                Psm[row*33 + col+1] = acc[mt][nt][h*2+1];
            }
        }
    __syncthreads();

    // ---- spline math: one thread per t ----
    int b = (int)(bt0 >> 13);
    int t = (int)(bt0 & (T-1)) + tid;
    float mask = xmask[(long long)b*T + t];

    float p[NJ];
    #pragma unroll
    for(int j=0;j<NJ;j++) p[j] = (Psm[tid*33 + j] + __ldg(proj_b + j)) * mask;

    const float inv_dn = 0.07216878364870323f;   // 1/sqrt(192)

    float cwv[BINS+1], wsv[BINS];
    {
        float m = -1e30f;
        #pragma unroll
        for(int j=0;j<BINS;j++) m = fmaxf(m, p[j]);
        float e[BINS]; float ssum = 0.f;
        #pragma unroll
        for(int j=0;j<BINS;j++){ e[j] = expf((p[j]-m)*inv_dn); ssum += e[j]; }
        float inv = 1.0f/ssum;
        float cum = 0.f;
        cwv[0] = -TAILV;
        #pragma unroll
        for(int j=0;j<BINS;j++){
            float wj = 1e-3f + 0.99f*e[j]*inv;
            cum += wj;
            cwv[j+1] = 2.0f*TAILV*cum - TAILV;
        }
        cwv[BINS] = TAILV;
        #pragma unroll
        for(int j=0;j<BINS;j++) wsv[j] = cwv[j+1]-cwv[j];
    }
    float chv[BINS+1], hsv[BINS];
    {
        float m = -1e30f;
        #pragma unroll
        for(int j=0;j<BINS;j++) m = fmaxf(m, p[BINS+j]);
        float e[BINS]; float ssum = 0.f;
        #pragma unroll
        for(int j=0;j<BINS;j++){ e[j] = expf((p[BINS+j]-m)*inv_dn); ssum += e[j]; }
        float inv = 1.0f/ssum;
        float cum = 0.f;
        chv[0] = -TAILV;
        #pragma unroll
        for(int j=0;j<BINS;j++){
            float hj = 1e-3f + 0.99f*e[j]*inv;
            cum += hj;
            chv[j+1] = 2.0f*TAILV*cum - TAILV;
        }
        chv[BINS] = TAILV;
        #pragma unroll
        for(int j=0;j<BINS;j++) hsv[j] = chv[j+1]-chv[j];
    }
    float derv[BINS+1];
    derv[0] = 1.0f; derv[BINS] = 1.0f;
    #pragma unroll
    for(int k=1;k<BINS;k++){
        float u = p[2*BINS + k - 1];
        float sp = (u > 20.f) ? u : log1pf(expf(u));
        derv[k] = 1e-3f + sp;
    }

    float xbv = x[((long long)b*2+1)*T + t];
    bool inside = (xbv >= -TAILV) && (xbv <= TAILV);
    float xc = fminf(fmaxf(xbv, -TAILV), TAILV);
    int idx = 0;
    #pragma unroll
    for(int j=0;j<BINS;j++) idx += (xc >= cwv[j]) ? 1 : 0;
    idx -= 1;
    idx = max(0, min(BINS-1, idx));

    // register gather via select chains (no local-memory spill)
    float icw=0.f, ibw=1.f, ich=0.f, ih=1.f, dk=1.f, dk1=1.f;
    #pragma unroll
    for(int j=0;j<BINS;j++){
        bool sel = (idx==j);
        icw = sel ? cwv[j]   : icw;
        ibw = sel ? wsv[j]   : ibw;
        ich = sel ? chv[j]   : ich;
        ih  = sel ? hsv[j]   : ih;
        dk  = sel ? derv[j]  : dk;
        dk1 = sel ? derv[j+1]: dk1;
    }

    float idl = ih/ibw;
    float th  = (xc - icw)/ibw;
    float t1m = th*(1.0f - th);
    float num = ih*(idl*th*th + dk*t1m);
    float den = idl + (dk + dk1 - 2.0f*idl)*t1m;
    float outv = ich + num/den;
    float omt = 1.0f - th;
    float dnum = idl*idl*(dk1*th*th + 2.0f*idl*t1m + dk*omt*omt);
    float lad = logf(dnum) - 2.0f*logf(den);

    float xb2 = inside ? outv : xbv;
    lad = inside ? lad : 0.0f;

    float xav = x[((long long)b*2)*T + t];
    out[(long long)b*2*T + t]     = xav*mask;
    out[(long long)b*2*T + T + t] = xb2*mask;

    float lv = lad*mask;
    #pragma unroll
    for(int o=16;o>0;o>>=1) lv += __shfl_xor_sync(0xffffffffu, lv, o);
    static __shared__ float red8[8];
    if(lane == 0) red8[wid] = lv;
    __syncthreads();
    if(tid == 0){
        float acc8 = red8[0]+red8[1]+red8[2]+red8[3]+red8[4]+red8[5]+red8[6]+red8[7];
        atomicAdd(out + (long long)B*2*T + b, acc8);
    }
}

// ---------------------------------------------------------------------------
extern "C" void kernel_launch(void* const* d_in, const int* in_sizes, int n_in,
                              void* d_out, int out_size)
{
    const float* x      = (const float*)d_in[0];
    const float* xmask  = (const float*)d_in[1];
    const float* in_w   = (const float*)d_in[2];
    const float* in_b   = (const float*)d_in[3];
    const float* dw_w   = (const float*)d_in[4];
    const float* dw_b   = (const float*)d_in[5];
    const float* ln1_g  = (const float*)d_in[6];
    const float* ln1_b  = (const float*)d_in[7];
    const float* pw_w   = (const float*)d_in[8];
    const float* pw_b   = (const float*)d_in[9];
    const float* ln2_g  = (const float*)d_in[10];
    const float* ln2_b  = (const float*)d_in[11];
    const float* proj_w = (const float*)d_in[12];
    const float* proj_b = (const float*)d_in[13];
    float* out = (float*)d_out;

    cudaFuncSetAttribute(k_gemm_mma, cudaFuncAttributeMaxDynamicSharedMemorySize, GEMM_SMEM_BYTES);
    cudaFuncSetAttribute(k_spline,   cudaFuncAttributeMaxDynamicSharedMemorySize, SPLINE_SMEM_BYTES);

    k_prep<<<(3*H*H + 255)/256, 256>>>(pw_w, proj_w, dw_w, out);
    k_init<<<(BT*H)/256, 256>>>(x, in_w, in_b);
    int dil = 1;
    for(int L=0; L<3; L++){
        k_conv<<<BT/32, 256>>>(L, dil, xmask, dw_b, ln1_g, ln1_b);
        k_gemm_mma<<<BT/128, 256, GEMM_SMEM_BYTES>>>(L, (L==2)?1:0, pw_b, ln2_g, ln2_b);
        dil *= 3;
    }
    k_spline<<<BT/256, 256, SPLINE_SMEM_BYTES>>>(x, xmask, proj_b, out);
}

// round 5
// speedup vs baseline: 3.8970x; 1.1187x over previous
#include <cuda_runtime.h>
#include <cuda_bf16.h>
#include <math.h>
#include <stdint.h>

#define B 32
#define T 8192
#define H 192
#define BT (B*T)
#define BINS 10
#define TAILV 5.0f
#define NJ 29

// residual stream (f32) and bf16 hi/lo stream, layout [b][t][c]
__device__ float g_x[(size_t)BT*H];
__device__ __align__(16) __nv_bfloat16 g_yh[(size_t)BT*H];
__device__ __align__(16) __nv_bfloat16 g_yl[(size_t)BT*H];
// padded pw weight image: [layer][hi/lo][o=192][pad 200] bf16
__device__ __align__(16) __nv_bfloat16 g_wp[3*2*192*200];
// padded proj weight image: [hi/lo][32][pad 200] bf16
__device__ __align__(16) __nv_bfloat16 g_pw[2*32*200];
// transposed depthwise weights: [layer][tap][c]
__device__ float g_dwt[3*3*192];

__device__ __forceinline__ float gelu_exact(float v){
    return 0.5f*v*(1.0f+erff(v*0.70710678118654752f));
}

__device__ __forceinline__ uint32_t smem_u32(const void* p){
    uint32_t a;
    asm("{ .reg .u64 t; cvta.to.shared.u64 t, %1; cvt.u32.u64 %0, t; }" : "=r"(a) : "l"(p));
    return a;
}

#define LDSM4(r, addr) \
    asm volatile("ldmatrix.sync.aligned.m8n8.x4.shared.b16 {%0,%1,%2,%3}, [%4];" \
        : "=r"((r)[0]),"=r"((r)[1]),"=r"((r)[2]),"=r"((r)[3]) : "r"(addr))

#define MMA16816(d, a, b0, b1) \
    asm volatile("mma.sync.aligned.m16n8k16.row.col.f32.bf16.bf16.f32 " \
        "{%0,%1,%2,%3},{%4,%5,%6,%7},{%8,%9},{%0,%1,%2,%3};" \
        : "+f"((d)[0]),"+f"((d)[1]),"+f"((d)[2]),"+f"((d)[3]) \
        : "r"((a)[0]),"r"((a)[1]),"r"((a)[2]),"r"((a)[3]), "r"(b0),"r"(b1))

#define CP16(dst, src) \
    asm volatile("cp.async.cg.shared.global [%0], [%1], 16;" :: "r"(dst), "l"(src))
#define CP_COMMIT asm volatile("cp.async.commit_group;" ::: "memory")
#define CP_WAIT2  asm volatile("cp.async.wait_group 2;" ::: "memory")
#define CP_WAIT1  asm volatile("cp.async.wait_group 1;" ::: "memory")
#define CP_WAIT0  asm volatile("cp.async.wait_group 0;" ::: "memory")

// ---------------------------------------------------------------------------
__global__ void k_zero(float* __restrict__ out){
    out[(long long)B*2*T + threadIdx.x] = 0.0f;
}

// prep: pw split image, proj split image, dw transpose
__global__ void k_prep(const float* __restrict__ pw_w,
                       const float* __restrict__ proj_w,
                       const float* __restrict__ dw_w)
{
    int i = blockIdx.x*256 + threadIdx.x;
    if (i < 3*H*H){
        int L = i / (H*H);
        int r = i - L*(H*H);
        int o = r / H, c = r - o*H;
        float w = pw_w[i];
        __nv_bfloat16 hb = __float2bfloat16(w);
        __nv_bfloat16 lb = __float2bfloat16(w - __bfloat162float(hb));
        g_wp[((size_t)(L*2+0)*192 + o)*200 + c] = hb;
        g_wp[((size_t)(L*2+1)*192 + o)*200 + c] = lb;
    }
    if (i < 2*32*200){
        int p = i / 6400;
        int rem = i - p*6400;
        int r = rem / 200, c = rem - r*200;
        float w = (r < NJ && c < H) ? proj_w[r*H + c] : 0.0f;
        __nv_bfloat16 hb = __float2bfloat16(w);
        __nv_bfloat16 lb = __float2bfloat16(w - __bfloat162float(hb));
        g_pw[i] = p ? lb : hb;
    }
    if (i < 3*3*H){
        int L = i / (3*H);
        int rem = i - L*(3*H);
        int c = rem / 3, k = rem - c*3;
        g_dwt[L*(3*H) + k*H + c] = dw_w[i];
    }
}

// ---------------------------------------------------------------------------
// depthwise dilated conv (K=3) + LN + exact gelu -> bf16 hi/lo.
// warp handles 4 consecutive t; lane owns 6 contiguous channels.
// layer 0: computes taps from x via in_w/in_b (fused k_init) and writes g_x.
__global__ void __launch_bounds__(256) k_conv(int layer, int dil,
    const float* __restrict__ x,
    const float* __restrict__ in_w, const float* __restrict__ in_b,
    const float* __restrict__ xmask,
    const float* __restrict__ dw_b,
    const float* __restrict__ ln_g, const float* __restrict__ ln_b)
{
    int wid = threadIdx.x >> 5, lane = threadIdx.x & 31;
    long long g0 = (long long)blockIdx.x*32 + wid*4;
    int b = (int)(g0 >> 13);
    int t0 = (int)(g0 & (T-1));
    int c0 = lane*6;
    bool first = (layer == 0);

    float w0[6], w1[6], w2[6], bbv[6], ggv[6], gbv[6];
    {
        const float* wt = g_dwt + layer*(3*H);
        #pragma unroll
        for(int p=0;p<3;p++){
            float2 a = *(const float2*)(wt + c0 + p*2);
            w0[p*2]=a.x; w0[p*2+1]=a.y;
            float2 bq = *(const float2*)(wt + H + c0 + p*2);
            w1[p*2]=bq.x; w1[p*2+1]=bq.y;
            float2 cq = *(const float2*)(wt + 2*H + c0 + p*2);
            w2[p*2]=cq.x; w2[p*2+1]=cq.y;
            float2 d = *(const float2*)(dw_b + layer*H + c0 + p*2);
            bbv[p*2]=d.x; bbv[p*2+1]=d.y;
            float2 e = *(const float2*)(ln_g + layer*H + c0 + p*2);
            ggv[p*2]=e.x; ggv[p*2+1]=e.y;
            float2 f = *(const float2*)(ln_b + layer*H + c0 + p*2);
            gbv[p*2]=f.x; gbv[p*2+1]=f.y;
        }
    }
    float iw[6], ib[6];
    if(first){
        #pragma unroll
        for(int p=0;p<3;p++){
            float2 a = *(const float2*)(in_w + c0 + p*2);
            iw[p*2]=a.x; iw[p*2+1]=a.y;
            float2 bq = *(const float2*)(in_b + c0 + p*2);
            ib[p*2]=bq.x; ib[p*2+1]=bq.y;
        }
    }
    const float* mrow = xmask + (long long)b*T;
    const float* xrowa = x + ((long long)b*2)*T;

    #pragma unroll
    for(int tt=0;tt<4;tt++){
        long long row = g0 + tt;
        int t = t0 + tt;
        int tm = t - dil, tp = t + dil;
        bool hm = (tm >= 0), hp = (tp < T);
        float mm = hm ? mrow[tm] : 0.f;
        float m0 = mrow[t];
        float mp = hp ? mrow[tp] : 0.f;

        float xm[6], xz[6], xp[6];
        if(first){
            float xam = hm ? xrowa[tm] : 0.f;
            float xa0 = xrowa[t];
            float xap = hp ? xrowa[tp] : 0.f;
            #pragma unroll
            for(int k=0;k<6;k++){
                xm[k] = iw[k]*xam + ib[k];
                xz[k] = iw[k]*xa0 + ib[k];
                xp[k] = iw[k]*xap + ib[k];
            }
            // write residual stream (unmasked h)
            float* gx = g_x + row*H + c0;
            #pragma unroll
            for(int p=0;p<3;p++)
                *(float2*)(gx + p*2) = make_float2(xz[p*2], xz[p*2+1]);
        } else {
            const float* base = g_x + row*H + c0;
            #pragma unroll
            for(int p=0;p<3;p++){
                float2 a = *(const float2*)(base + p*2);
                xz[p*2]=a.x; xz[p*2+1]=a.y;
            }
            if(hm){
                const float* bmp = base - (long long)dil*H;
                #pragma unroll
                for(int p=0;p<3;p++){
                    float2 a = *(const float2*)(bmp + p*2);
                    xm[p*2]=a.x; xm[p*2+1]=a.y;
                }
            } else {
                #pragma unroll
                for(int k=0;k<6;k++) xm[k]=0.f;
            }
            if(hp){
                const float* bpp = base + (long long)dil*H;
                #pragma unroll
                for(int p=0;p<3;p++){
                    float2 a = *(const float2*)(bpp + p*2);
                    xp[p*2]=a.x; xp[p*2+1]=a.y;
                }
            } else {
                #pragma unroll
                for(int k=0;k<6;k++) xp[k]=0.f;
            }
        }

        float v[6];
        float s=0.f, sq=0.f;
        #pragma unroll
        for(int k=0;k<6;k++){
            float r = w0[k]*(xm[k]*mm) + w1[k]*(xz[k]*m0) + w2[k]*(xp[k]*mp) + bbv[k];
            v[k]=r; s+=r; sq+=r*r;
        }
        #pragma unroll
        for(int o=16;o>0;o>>=1){
            s  += __shfl_xor_sync(0xffffffffu, s,  o);
            sq += __shfl_xor_sync(0xffffffffu, sq, o);
        }
        float mu = s*(1.0f/H);
        float rs = rsqrtf(sq*(1.0f/H) - mu*mu + 1e-5f);

        uint32_t hw[3], lw[3];
        #pragma unroll
        for(int p=0;p<3;p++){
            float y0 = gelu_exact((v[p*2]  -mu)*rs*ggv[p*2]   + gbv[p*2]);
            float y1 = gelu_exact((v[p*2+1]-mu)*rs*ggv[p*2+1] + gbv[p*2+1]);
            __nv_bfloat16 h0 = __float2bfloat16(y0);
            __nv_bfloat16 h1 = __float2bfloat16(y1);
            __nv_bfloat16 l0 = __float2bfloat16(y0 - __bfloat162float(h0));
            __nv_bfloat16 l1 = __float2bfloat16(y1 - __bfloat162float(h1));
            __nv_bfloat162 ph = __halves2bfloat162(h0,h1);
            __nv_bfloat162 pl = __halves2bfloat162(l0,l1);
            hw[p] = *(uint32_t*)&ph;
            lw[p] = *(uint32_t*)&pl;
        }
        uint32_t* oh = (uint32_t*)(g_yh + row*H + c0);
        uint32_t* ol = (uint32_t*)(g_yl + row*H + c0);
        oh[0]=hw[0]; oh[1]=hw[1]; oh[2]=hw[2];
        ol[0]=lw[0]; ol[1]=lw[1]; ol[2]=lw[2];
    }
}

// ---------------------------------------------------------------------------
// warp-MMA GEMM: D[t(128), o(192)] = Y . W^T, split-bf16 (3 passes)
// + fused bias + LN(over o) + gelu + residual into g_x.
// 512 threads, 16 warps: 4 in M (32 rows each) x 4 in N (48 cols each).
#define BSM_HI   0
#define BSM_LO   76800
#define ABUF     153600
#define PAROFF   (ABUF + 3*20480)
#define GEMM_SMEM_BYTES (PAROFF + 2304)

__global__ void __launch_bounds__(512,1) k_gemm_mma(int layer, int last,
    const float* __restrict__ pw_b,
    const float* __restrict__ ln_g, const float* __restrict__ ln_b)
{
    extern __shared__ char smem[];
    uint32_t sbase = smem_u32(smem);
    int tid = threadIdx.x;
    int wid = tid >> 5, lane = tid & 31;
    int wm = wid & 3, wn = wid >> 2;        // 4 warps in M, 4 in N
    int q = lane >> 2, qi = lane & 3;
    long long bt0 = (long long)blockIdx.x * 128;

    // weight image (hi+lo, 153600B) into smem
    {
        const uint4* src = (const uint4*)(g_wp + (size_t)layer*2*192*200);
        uint4* dst = (uint4*)smem;
        #pragma unroll 4
        for(int i=tid;i<9600;i+=512) dst[i] = src[i];
    }
    float* par = (float*)(smem + PAROFF);
    if(tid < 192){
        par[tid]       = pw_b[layer*H + tid];
        par[192 + tid] = ln_g[layer*H + tid];
        par[384 + tid] = ln_b[layer*H + tid];
    }

    // A loaders: chunk = 32 k; 512 ids: row=tid>>2, seg=tid&3
    int rowL = tid >> 2, segL = tid & 3;
    uint32_t dstOff = (uint32_t)rowL*80 + (uint32_t)segL*16;
    const __nv_bfloat16* srcHb = g_yh + (bt0+rowL)*H + segL*8;
    const __nv_bfloat16* srcLb = g_yl + (bt0+rowL)*H + segL*8;

#define ISSUE_CHUNK(cc, st) do { \
    uint32_t _ah = sbase + ABUF + (st)*20480; \
    uint32_t _al = _ah + 10240; \
    int _k = (cc)*32; \
    CP16(_ah + dstOff, srcHb + _k); \
    CP16(_al + dstOff, srcLb + _k); \
    CP_COMMIT; \
} while(0)

    ISSUE_CHUNK(0, 0);
    ISSUE_CHUNK(1, 1);
    ISSUE_CHUNK(2, 2);

    int g2 = lane >> 3, lr = lane & 7;
    uint32_t aOff[2];
    #pragma unroll
    for(int mt=0;mt<2;mt++)
        aOff[mt] = (uint32_t)(wm*32 + mt*16 + (g2&1)*8 + lr)*80 + (uint32_t)(g2>>1)*16;
    uint32_t bOff[3];
    #pragma unroll
    for(int i=0;i<3;i++)
        bOff[i] = (uint32_t)(wn*48 + i*16 + (g2>>1)*8 + lr)*400 + (uint32_t)(g2&1)*16;

    float acc[2][6][4];
    #pragma unroll
    for(int mt=0;mt<2;mt++)
        #pragma unroll
        for(int nt=0;nt<6;nt++)
            #pragma unroll
            for(int r=0;r<4;r++) acc[mt][nt][r] = 0.f;

    #pragma unroll 1
    for(int c=0;c<6;c++){
        if(c<4){ CP_WAIT2; } else if(c==4){ CP_WAIT1; } else { CP_WAIT0; }
        __syncthreads();
        int st = c % 3;
        uint32_t abufH = sbase + ABUF + st*20480;
        uint32_t abufL = abufH + 10240;
        #pragma unroll
        for(int ks=0;ks<2;ks++){
            uint32_t kA = ks*32;
            uint32_t kB = (uint32_t)c*64 + ks*32;
            uint32_t ah[2][4], al[2][4], bb[3][4];
            LDSM4(ah[0], abufH + aOff[0] + kA);
            LDSM4(ah[1], abufH + aOff[1] + kA);
            LDSM4(al[0], abufL + aOff[0] + kA);
            LDSM4(al[1], abufL + aOff[1] + kA);
            #pragma unroll
            for(int i=0;i<3;i++) LDSM4(bb[i], sbase + BSM_HI + bOff[i] + kB);
            #pragma unroll
            for(int mt=0;mt<2;mt++)
                #pragma unroll
                for(int i=0;i<3;i++){
                    MMA16816(acc[mt][2*i],   ah[mt], bb[i][0], bb[i][1]);
                    MMA16816(acc[mt][2*i+1], ah[mt], bb[i][2], bb[i][3]);
                    MMA16816(acc[mt][2*i],   al[mt], bb[i][0], bb[i][1]);
                    MMA16816(acc[mt][2*i+1], al[mt], bb[i][2], bb[i][3]);
                }
            #pragma unroll
            for(int i=0;i<3;i++) LDSM4(bb[i], sbase + BSM_LO + bOff[i] + kB);
            #pragma unroll
            for(int mt=0;mt<2;mt++)
                #pragma unroll
                for(int i=0;i<3;i++){
                    MMA16816(acc[mt][2*i],   ah[mt], bb[i][0], bb[i][1]);
                    MMA16816(acc[mt][2*i+1], ah[mt], bb[i][2], bb[i][3]);
                }
        }
        __syncthreads();
        if(c<3) ISSUE_CHUNK(c+3, st);
    }

    // ---------------- epilogue: bias + LN + gelu + residual ----------------
    float* red1 = (float*)(smem + ABUF);         // 512
    float* red2 = red1 + 512;                    // 512
    float* musm = red1 + 1024;                   // 128
    float* rssm = red1 + 1152;                   // 128

    float s1[2][2] = {{0.f,0.f},{0.f,0.f}};
    float s2[2][2] = {{0.f,0.f},{0.f,0.f}};
    #pragma unroll
    for(int mt=0;mt<2;mt++)
        #pragma unroll
        for(int nt=0;nt<6;nt++){
            int col = wn*48 + nt*8 + qi*2;
            float b0 = par[col], b1 = par[col+1];
            acc[mt][nt][0] += b0; acc[mt][nt][1] += b1;
            acc[mt][nt][2] += b0; acc[mt][nt][3] += b1;
            #pragma unroll
            for(int h=0;h<2;h++){
                float v0 = acc[mt][nt][h*2], v1 = acc[mt][nt][h*2+1];
                s1[mt][h] += v0 + v1;
                s2[mt][h] += v0*v0 + v1*v1;
            }
        }
    #pragma unroll
    for(int mt=0;mt<2;mt++)
        #pragma unroll
        for(int h=0;h<2;h++){
            float a = s1[mt][h], b2 = s2[mt][h];
            a  += __shfl_xor_sync(0xffffffffu, a, 1);
            a  += __shfl_xor_sync(0xffffffffu, a, 2);
            b2 += __shfl_xor_sync(0xffffffffu, b2, 1);
            b2 += __shfl_xor_sync(0xffffffffu, b2, 2);
            if(qi==0){
                int row = wm*32 + mt*16 + h*8 + q;
                red1[wn*128 + row] = a;
                red2[wn*128 + row] = b2;
            }
        }
    __syncthreads();
    if(tid < 128){
        float t1 = red1[tid] + red1[128+tid] + red1[256+tid] + red1[384+tid];
        float t2 = red2[tid] + red2[128+tid] + red2[256+tid] + red2[384+tid];
        float mu = t1*(1.0f/H);
        musm[tid] = mu;
        rssm[tid] = rsqrtf(t2*(1.0f/H) - mu*mu + 1e-5f);
    }
    __syncthreads();

    const float* lg = par + 192;
    const float* lb = par + 384;
    #pragma unroll
    for(int mt=0;mt<2;mt++)
        #pragma unroll
        for(int h=0;h<2;h++){
            int row = wm*32 + mt*16 + h*8 + q;
            float mu = musm[row], rs = rssm[row];
            float* xrow = g_x + (bt0+row)*H;
            __nv_bfloat16* yh = g_yh + (bt0+row)*H;
            __nv_bfloat16* yl = g_yl + (bt0+row)*H;
            #pragma unroll
            for(int nt=0;nt<6;nt++){
                int col = wn*48 + nt*8 + qi*2;
                float v0 = acc[mt][nt][h*2], v1 = acc[mt][nt][h*2+1];
                float2 res = *(float2*)(xrow + col);
                float o0 = gelu_exact((v0-mu)*rs*lg[col]   + lb[col])   + res.x;
                float o1 = gelu_exact((v1-mu)*rs*lg[col+1] + lb[col+1]) + res.y;
                *(float2*)(xrow + col) = make_float2(o0, o1);
                if(last){
                    __nv_bfloat16 h0 = __float2bfloat16(o0);
                    __nv_bfloat16 h1 = __float2bfloat16(o1);
                    __nv_bfloat16 l0 = __float2bfloat16(o0 - __bfloat162float(h0));
                    __nv_bfloat16 l1 = __float2bfloat16(o1 - __bfloat162float(h1));
                    __nv_bfloat162 ph = __halves2bfloat162(h0,h1);
                    __nv_bfloat162 pl = __halves2bfloat162(l0,l1);
                    *(__nv_bfloat162*)(yh + col) = ph;
                    *(__nv_bfloat162*)(yl + col) = pl;
                }
            }
        }
}

// ---------------------------------------------------------------------------
// spline: P = x_final . proj_w^T via split-bf16 mma, then RQ spline + logdet
#define SP_PWHI 0
#define SP_PWLO 12800
#define SP_ABUF 25600
#define SP_P    25600
#define SPLINE_SMEM_BYTES (25600 + 2*40960)

__global__ void __launch_bounds__(256) k_spline(
    const float* __restrict__ x, const float* __restrict__ xmask,
    const float* __restrict__ proj_b,
    float* __restrict__ out)
{
    extern __shared__ char smem[];
    uint32_t sbase = smem_u32(smem);
    int tid = threadIdx.x;
    int wid = tid >> 5, lane = tid & 31;
    int q = lane >> 2, qi = lane & 3;
    long long bt0 = (long long)blockIdx.x * 256;

    {
        const uint4* src = (const uint4*)g_pw;
        uint4* dst = (uint4*)smem;
        #pragma unroll
        for(int i=tid;i<1600;i+=256) dst[i] = src[i];
    }

    int rows[4], segs[4];
    #pragma unroll
    for(int m=0;m<4;m++){
        int id = tid + m*256;
        rows[m] = id >> 2; segs[m] = id & 3;
    }

#define SP_ISSUE(cc, st) do { \
    uint32_t _ah = sbase + SP_ABUF + (st)*40960; \
    uint32_t _al = _ah + 20480; \
    int _k = (cc)*32; \
    _Pragma("unroll") \
    for(int m=0;m<4;m++){ \
        uint32_t d = (uint32_t)rows[m]*80 + (uint32_t)segs[m]*16; \
        CP16(_ah + d, g_yh + (bt0+rows[m])*H + segs[m]*8 + _k); \
        CP16(_al + d, g_yl + (bt0+rows[m])*H + segs[m]*8 + _k); \
    } \
    CP_COMMIT; \
} while(0)

    SP_ISSUE(0, 0);
    SP_ISSUE(1, 1);

    int g2 = lane >> 3, lr = lane & 7;
    uint32_t aOff[2];
    #pragma unroll
    for(int mt=0;mt<2;mt++)
        aOff[mt] = (uint32_t)(wid*32 + mt*16 + (g2&1)*8 + lr)*80 + (uint32_t)(g2>>1)*16;
    uint32_t bOff[2];
    #pragma unroll
    for(int i=0;i<2;i++)
        bOff[i] = (uint32_t)(i*16 + (g2>>1)*8 + lr)*400 + (uint32_t)(g2&1)*16;

    float acc[2][4][4];
    #pragma unroll
    for(int mt=0;mt<2;mt++)
        #pragma unroll
        for(int nt=0;nt<4;nt++)
            #pragma unroll
            for(int r=0;r<4;r++) acc[mt][nt][r]=0.f;

    #pragma unroll 1
    for(int c=0;c<6;c++){
        if(c<5){ CP_WAIT1; } else { CP_WAIT0; }
        __syncthreads();
        uint32_t abufH = sbase + SP_ABUF + (c&1)*40960;
        uint32_t abufL = abufH + 20480;
        #pragma unroll
        for(int ks=0;ks<2;ks++){
            uint32_t kA = ks*32;
            uint32_t kB = (uint32_t)c*64 + ks*32;
            uint32_t ah[2][4], al[2][4], bb[2][4];
            LDSM4(ah[0], abufH + aOff[0] + kA);
            LDSM4(ah[1], abufH + aOff[1] + kA);
            LDSM4(al[0], abufL + aOff[0] + kA);
            LDSM4(al[1], abufL + aOff[1] + kA);
            LDSM4(bb[0], sbase + SP_PWHI + bOff[0] + kB);
            LDSM4(bb[1], sbase + SP_PWHI + bOff[1] + kB);
            #pragma unroll
            for(int mt=0;mt<2;mt++)
                #pragma unroll
                for(int i=0;i<2;i++){
                    MMA16816(acc[mt][2*i],   ah[mt], bb[i][0], bb[i][1]);
                    MMA16816(acc[mt][2*i+1], ah[mt], bb[i][2], bb[i][3]);
                    MMA16816(acc[mt][2*i],   al[mt], bb[i][0], bb[i][1]);
                    MMA16816(acc[mt][2*i+1], al[mt], bb[i][2], bb[i][3]);
                }
            LDSM4(bb[0], sbase + SP_PWLO + bOff[0] + kB);
            LDSM4(bb[1], sbase + SP_PWLO + bOff[1] + kB);
            #pragma unroll
            for(int mt=0;mt<2;mt++)
                #pragma unroll
                for(int i=0;i<2;i++){
                    MMA16816(acc[mt][2*i],   ah[mt], bb[i][0], bb[i][1]);
                    MMA16816(acc[mt][2*i+1], ah[mt], bb[i][2], bb[i][3]);
                }
        }
        __syncthreads();
        if(c<4) SP_ISSUE(c+2, c&1);
    }

    float* Psm = (float*)(smem + SP_P);
    #pragma unroll
    for(int mt=0;mt<2;mt++)
        #pragma unroll
        for(int h=0;h<2;h++){
            int row = wid*32 + mt*16 + h*8 + q;
            #pragma unroll
            for(int nt=0;nt<4;nt++){
                int col = nt*8 + qi*2;
                Psm[row*33 + col]   = acc[mt][nt][h*2];
                Psm[row*33 + col+1] = acc[mt][nt][h*2+1];
            }
        }
    __syncthreads();

    int b = (int)(bt0 >> 13);
    int t = (int)(bt0 & (T-1)) + tid;
    float mask = xmask[(long long)b*T + t];

    float p[NJ];
    #pragma unroll
    for(int j=0;j<NJ;j++) p[j] = (Psm[tid*33 + j] + __ldg(proj_b + j)) * mask;

    const float inv_dn = 0.07216878364870323f;   // 1/sqrt(192)

    float cwv[BINS+1], wsv[BINS];
    {
        float m = -1e30f;
        #pragma unroll
        for(int j=0;j<BINS;j++) m = fmaxf(m, p[j]);
        float e[BINS]; float ssum = 0.f;
        #pragma unroll
        for(int j=0;j<BINS;j++){ e[j] = expf((p[j]-m)*inv_dn); ssum += e[j]; }
        float inv = 1.0f/ssum;
        float cum = 0.f;
        cwv[0] = -TAILV;
        #pragma unroll
        for(int j=0;j<BINS;j++){
            float wj = 1e-3f + 0.99f*e[j]*inv;
            cum += wj;
            cwv[j+1] = 2.0f*TAILV*cum - TAILV;
        }
        cwv[BINS] = TAILV;
        #pragma unroll
        for(int j=0;j<BINS;j++) wsv[j] = cwv[j+1]-cwv[j];
    }
    float chv[BINS+1], hsv[BINS];
    {
        float m = -1e30f;
        #pragma unroll
        for(int j=0;j<BINS;j++) m = fmaxf(m, p[BINS+j]);
        float e[BINS]; float ssum = 0.f;
        #pragma unroll
        for(int j=0;j<BINS;j++){ e[j] = expf((p[BINS+j]-m)*inv_dn); ssum += e[j]; }
        float inv = 1.0f/ssum;
        float cum = 0.f;
        chv[0] = -TAILV;
        #pragma unroll
        for(int j=0;j<BINS;j++){
            float hj = 1e-3f + 0.99f*e[j]*inv;
            cum += hj;
            chv[j+1] = 2.0f*TAILV*cum - TAILV;
        }
        chv[BINS] = TAILV;
        #pragma unroll
        for(int j=0;j<BINS;j++) hsv[j] = chv[j+1]-chv[j];
    }
    float derv[BINS+1];
    derv[0] = 1.0f; derv[BINS] = 1.0f;
    #pragma unroll
    for(int k=1;k<BINS;k++){
        float u = p[2*BINS + k - 1];
        float sp = (u > 20.f) ? u : log1pf(expf(u));
        derv[k] = 1e-3f + sp;
    }

    float xbv = x[((long long)b*2+1)*T + t];
    bool inside = (xbv >= -TAILV) && (xbv <= TAILV);
    float xc = fminf(fmaxf(xbv, -TAILV), TAILV);
    int idx = 0;
    #pragma unroll
    for(int j=0;j<BINS;j++) idx += (xc >= cwv[j]) ? 1 : 0;
    idx -= 1;
    idx = max(0, min(BINS-1, idx));

    float icw=0.f, ibw=1.f, ich=0.f, ih=1.f, dk=1.f, dk1=1.f;
    #pragma unroll
    for(int j=0;j<BINS;j++){
        bool sel = (idx==j);
        icw = sel ? cwv[j]   : icw;
        ibw = sel ? wsv[j]   : ibw;
        ich = sel ? chv[j]   : ich;
        ih  = sel ? hsv[j]   : ih;
        dk  = sel ? derv[j]  : dk;
        dk1 = sel ? derv[j+1]: dk1;
    }

    float idl = ih/ibw;
    float th  = (xc - icw)/ibw;
    float t1m = th*(1.0f - th);
    float num = ih*(idl*th*th + dk*t1m);
    float den = idl + (dk + dk1 - 2.0f*idl)*t1m;
    float outv = ich + num/den;
    float omt = 1.0f - th;
    float dnum = idl*idl*(dk1*th*th + 2.0f*idl*t1m + dk*omt*omt);
    float lad = logf(dnum) - 2.0f*logf(den);

    float xb2 = inside ? outv : xbv;
    lad = inside ? lad : 0.0f;

    float xav = x[((long long)b*2)*T + t];
    out[(long long)b*2*T + t]     = xav*mask;
    out[(long long)b*2*T + T + t] = xb2*mask;

    float lv = lad*mask;
    #pragma unroll
    for(int o=16;o>0;o>>=1) lv += __shfl_xor_sync(0xffffffffu, lv, o);
    static __shared__ float red8[8];
    if(lane == 0) red8[wid] = lv;
    __syncthreads();
    if(tid == 0){
        float acc8 = red8[0]+red8[1]+red8[2]+red8[3]+red8[4]+red8[5]+red8[6]+red8[7];
        atomicAdd(out + (long long)B*2*T + b, acc8);
    }
}

// ---------------------------------------------------------------------------
extern "C" void kernel_launch(void* const* d_in, const int* in_sizes, int n_in,
                              void* d_out, int out_size)
{
    const float* x      = (const float*)d_in[0];
    const float* xmask  = (const float*)d_in[1];
    const float* in_w   = (const float*)d_in[2];
    const float* in_b   = (const float*)d_in[3];
    const float* dw_w   = (const float*)d_in[4];
    const float* dw_b   = (const float*)d_in[5];
    const float* ln1_g  = (const float*)d_in[6];
    const float* ln1_b  = (const float*)d_in[7];
    const float* pw_w   = (const float*)d_in[8];
    const float* pw_b   = (const float*)d_in[9];
    const float* ln2_g  = (const float*)d_in[10];
    const float* ln2_b  = (const float*)d_in[11];
    const float* proj_w = (const float*)d_in[12];
    const float* proj_b = (const float*)d_in[13];
    float* out = (float*)d_out;

    cudaFuncSetAttribute(k_gemm_mma, cudaFuncAttributeMaxDynamicSharedMemorySize, GEMM_SMEM_BYTES);
    cudaFuncSetAttribute(k_spline,   cudaFuncAttributeMaxDynamicSharedMemorySize, SPLINE_SMEM_BYTES);

    k_zero<<<1, 32>>>(out);
    k_prep<<<(3*H*H + 255)/256, 256>>>(pw_w, proj_w, dw_w);
    int dil = 1;
    for(int L=0; L<3; L++){
        k_conv<<<BT/32, 256>>>(L, dil, x, in_w, in_b, xmask, dw_b, ln1_g, ln1_b);
        k_gemm_mma<<<BT/128, 512, GEMM_SMEM_BYTES>>>(L, (L==2)?1:0, pw_b, ln2_g, ln2_b);
        dil *= 3;
    }
    k_spline<<<BT/256, 256, SPLINE_SMEM_BYTES>>>(x, xmask, proj_b, out);
}

// round 6
// speedup vs baseline: 4.0995x; 1.0520x over previous
#include <cuda_runtime.h>
#include <cuda_bf16.h>
#include <math.h>
#include <stdint.h>

#define B 32
#define T 8192
#define H 192
#define BT (B*T)
#define BINS 10
#define TAILV 5.0f
#define NJ 29

// residual stream (f32) and bf16 hi/lo stream, layout [b][t][c]
__device__ float g_x[(size_t)BT*H];
__device__ __align__(16) __nv_bfloat16 g_yh[(size_t)BT*H];
__device__ __align__(16) __nv_bfloat16 g_yl[(size_t)BT*H];
// chunk-ordered pw weight image: [layer][chunk(6)][dtype(2)][o=192][seg(4)][8 bf16]
// = per layer 6*2*192*32 bf16; per chunk-stage 1536 16B-segments
__device__ __align__(16) __nv_bfloat16 g_wr[3*6*2*192*32];
// padded proj weight image: [hi/lo][32][pad 200] bf16
__device__ __align__(16) __nv_bfloat16 g_pw[2*32*200];
// transposed depthwise weights: [layer][tap][c]
__device__ float g_dwt[3*3*192];

__device__ __forceinline__ float gelu_exact(float v){
    return 0.5f*v*(1.0f+erff(v*0.70710678118654752f));
}

__device__ __forceinline__ uint32_t smem_u32(const void* p){
    uint32_t a;
    asm("{ .reg .u64 t; cvta.to.shared.u64 t, %1; cvt.u32.u64 %0, t; }" : "=r"(a) : "l"(p));
    return a;
}

#define LDSM4(r, addr) \
    asm volatile("ldmatrix.sync.aligned.m8n8.x4.shared.b16 {%0,%1,%2,%3}, [%4];" \
        : "=r"((r)[0]),"=r"((r)[1]),"=r"((r)[2]),"=r"((r)[3]) : "r"(addr))

#define MMA16816(d, a, b0, b1) \
    asm volatile("mma.sync.aligned.m16n8k16.row.col.f32.bf16.bf16.f32 " \
        "{%0,%1,%2,%3},{%4,%5,%6,%7},{%8,%9},{%0,%1,%2,%3};" \
        : "+f"((d)[0]),"+f"((d)[1]),"+f"((d)[2]),"+f"((d)[3]) \
        : "r"((a)[0]),"r"((a)[1]),"r"((a)[2]),"r"((a)[3]), "r"(b0),"r"(b1))

#define CP16(dst, src) \
    asm volatile("cp.async.cg.shared.global [%0], [%1], 16;" :: "r"(dst), "l"(src))
#define CP_COMMIT asm volatile("cp.async.commit_group;" ::: "memory")
#define CP_WAIT1  asm volatile("cp.async.wait_group 1;" ::: "memory")
#define CP_WAIT0  asm volatile("cp.async.wait_group 0;" ::: "memory")

// ---------------------------------------------------------------------------
__global__ void k_zero(float* __restrict__ out){
    out[(long long)B*2*T + threadIdx.x] = 0.0f;
}

// prep: pw chunk-ordered split image, proj split image, dw transpose
__global__ void k_prep(const float* __restrict__ pw_w,
                       const float* __restrict__ proj_w,
                       const float* __restrict__ dw_w)
{
    int i = blockIdx.x*256 + threadIdx.x;
    if (i < 3*H*H){
        int L = i / (H*H);
        int r = i - L*(H*H);
        int o = r / H, k = r - o*H;
        float w = pw_w[i];
        __nv_bfloat16 hb = __float2bfloat16(w);
        __nv_bfloat16 lb = __float2bfloat16(w - __bfloat162float(hb));
        int c = k >> 5;             // chunk
        int s = (k >> 3) & 3;       // 16B segment within chunk
        int j = k & 7;              // element within segment
        size_t base = ((size_t)(L*6 + c)*1536 + (size_t)o*4 + s)*8 + j;
        g_wr[base]          = hb;           // dtype 0 (hi)
        g_wr[base + 6144]   = lb;           // dtype 1 (lo): +768 segs * 8
    }
    if (i < 2*32*200){
        int p = i / 6400;
        int rem = i - p*6400;
        int r = rem / 200, c = rem - r*200;
        float w = (r < NJ && c < H) ? proj_w[r*H + c] : 0.0f;
        __nv_bfloat16 hb = __float2bfloat16(w);
        __nv_bfloat16 lb = __float2bfloat16(w - __bfloat162float(hb));
        g_pw[i] = p ? lb : hb;
    }
    if (i < 3*3*H){
        int L = i / (3*H);
        int rem = i - L*(3*H);
        int c = rem / 3, k = rem - c*3;
        g_dwt[L*(3*H) + k*H + c] = dw_w[i];
    }
}

// ---------------------------------------------------------------------------
// depthwise dilated conv (K=3) + LN + exact gelu -> bf16 hi/lo.
// warp handles 4 consecutive t; lane owns 6 contiguous channels.
// layer 0: computes taps from x via in_w/in_b (fused init) and writes g_x.
__global__ void __launch_bounds__(256) k_conv(int layer, int dil,
    const float* __restrict__ x,
    const float* __restrict__ in_w, const float* __restrict__ in_b,
    const float* __restrict__ xmask,
    const float* __restrict__ dw_b,
    const float* __restrict__ ln_g, const float* __restrict__ ln_b)
{
    int wid = threadIdx.x >> 5, lane = threadIdx.x & 31;
    long long g0 = (long long)blockIdx.x*32 + wid*4;
    int b = (int)(g0 >> 13);
    int t0 = (int)(g0 & (T-1));
    int c0 = lane*6;
    bool first = (layer == 0);

    float w0[6], w1[6], w2[6], bbv[6], ggv[6], gbv[6];
    {
        const float* wt = g_dwt + layer*(3*H);
        #pragma unroll
        for(int p=0;p<3;p++){
            float2 a = *(const float2*)(wt + c0 + p*2);
            w0[p*2]=a.x; w0[p*2+1]=a.y;
            float2 bq = *(const float2*)(wt + H + c0 + p*2);
            w1[p*2]=bq.x; w1[p*2+1]=bq.y;
            float2 cq = *(const float2*)(wt + 2*H + c0 + p*2);
            w2[p*2]=cq.x; w2[p*2+1]=cq.y;
            float2 d = *(const float2*)(dw_b + layer*H + c0 + p*2);
            bbv[p*2]=d.x; bbv[p*2+1]=d.y;
            float2 e = *(const float2*)(ln_g + layer*H + c0 + p*2);
            ggv[p*2]=e.x; ggv[p*2+1]=e.y;
            float2 f = *(const float2*)(ln_b + layer*H + c0 + p*2);
            gbv[p*2]=f.x; gbv[p*2+1]=f.y;
        }
    }
    float iw[6], ib[6];
    if(first){
        #pragma unroll
        for(int p=0;p<3;p++){
            float2 a = *(const float2*)(in_w + c0 + p*2);
            iw[p*2]=a.x; iw[p*2+1]=a.y;
            float2 bq = *(const float2*)(in_b + c0 + p*2);
            ib[p*2]=bq.x; ib[p*2+1]=bq.y;
        }
    }
    const float* mrow = xmask + (long long)b*T;
    const float* xrowa = x + ((long long)b*2)*T;

    #pragma unroll
    for(int tt=0;tt<4;tt++){
        long long row = g0 + tt;
        int t = t0 + tt;
        int tm = t - dil, tp = t + dil;
        bool hm = (tm >= 0), hp = (tp < T);
        float mm = hm ? mrow[tm] : 0.f;
        float m0 = mrow[t];
        float mp = hp ? mrow[tp] : 0.f;

        float xm[6], xz[6], xp[6];
        if(first){
            float xam = hm ? xrowa[tm] : 0.f;
            float xa0 = xrowa[t];
            float xap = hp ? xrowa[tp] : 0.f;
            #pragma unroll
            for(int k=0;k<6;k++){
                xm[k] = iw[k]*xam + ib[k];
                xz[k] = iw[k]*xa0 + ib[k];
                xp[k] = iw[k]*xap + ib[k];
            }
            float* gx = g_x + row*H + c0;
            #pragma unroll
            for(int p=0;p<3;p++)
                *(float2*)(gx + p*2) = make_float2(xz[p*2], xz[p*2+1]);
        } else {
            const float* base = g_x + row*H + c0;
            #pragma unroll
            for(int p=0;p<3;p++){
                float2 a = *(const float2*)(base + p*2);
                xz[p*2]=a.x; xz[p*2+1]=a.y;
            }
            if(hm){
                const float* bmp = base - (long long)dil*H;
                #pragma unroll
                for(int p=0;p<3;p++){
                    float2 a = *(const float2*)(bmp + p*2);
                    xm[p*2]=a.x; xm[p*2+1]=a.y;
                }
            } else {
                #pragma unroll
                for(int k=0;k<6;k++) xm[k]=0.f;
            }
            if(hp){
                const float* bpp = base + (long long)dil*H;
                #pragma unroll
                for(int p=0;p<3;p++){
                    float2 a = *(const float2*)(bpp + p*2);
                    xp[p*2]=a.x; xp[p*2+1]=a.y;
                }
            } else {
                #pragma unroll
                for(int k=0;k<6;k++) xp[k]=0.f;
            }
        }

        float v[6];
        float s=0.f, sq=0.f;
        #pragma unroll
        for(int k=0;k<6;k++){
            float r = w0[k]*(xm[k]*mm) + w1[k]*(xz[k]*m0) + w2[k]*(xp[k]*mp) + bbv[k];
            v[k]=r; s+=r; sq+=r*r;
        }
        #pragma unroll
        for(int o=16;o>0;o>>=1){
            s  += __shfl_xor_sync(0xffffffffu, s,  o);
            sq += __shfl_xor_sync(0xffffffffu, sq, o);
        }
        float mu = s*(1.0f/H);
        float rs = rsqrtf(sq*(1.0f/H) - mu*mu + 1e-5f);

        uint32_t hw[3], lw[3];
        #pragma unroll
        for(int p=0;p<3;p++){
            float y0 = gelu_exact((v[p*2]  -mu)*rs*ggv[p*2]   + gbv[p*2]);
            float y1 = gelu_exact((v[p*2+1]-mu)*rs*ggv[p*2+1] + gbv[p*2+1]);
            __nv_bfloat16 h0 = __float2bfloat16(y0);
            __nv_bfloat16 h1 = __float2bfloat16(y1);
            __nv_bfloat16 l0 = __float2bfloat16(y0 - __bfloat162float(h0));
            __nv_bfloat16 l1 = __float2bfloat16(y1 - __bfloat162float(h1));
            __nv_bfloat162 ph = __halves2bfloat162(h0,h1);
            __nv_bfloat162 pl = __halves2bfloat162(l0,l1);
            hw[p] = *(uint32_t*)&ph;
            lw[p] = *(uint32_t*)&pl;
        }
        uint32_t* oh = (uint32_t*)(g_yh + row*H + c0);
        uint32_t* ol = (uint32_t*)(g_yl + row*H + c0);
        oh[0]=hw[0]; oh[1]=hw[1]; oh[2]=hw[2];
        ol[0]=lw[0]; ol[1]=lw[1]; ol[2]=lw[2];
    }
}

// ---------------------------------------------------------------------------
// warp-MMA GEMM: D[t(64), o(192)] = Y . W^T, split-bf16 (3 passes)
// + fused bias + LN(over o) + gelu + residual into g_x.
// 256 threads, 8 warps (2M x 4N), warp tile 32x48. BOTH A and B streamed via
// cp.async 2-stage rings -> smem 84.2KB -> 2 CTAs/SM.
#define BR      0
#define BSTG_D  15360
#define BSTG    30720
#define AR      61440
#define ASTG_D  5120
#define ASTG    10240
#define PAR_OFF 81920
#define GEMM_SMEM_BYTES (PAR_OFF + 2304)

__global__ void __launch_bounds__(256,2) k_gemm_mma(int layer, int last,
    const float* __restrict__ pw_b,
    const float* __restrict__ ln_g, const float* __restrict__ ln_b)
{
    extern __shared__ char smem[];
    uint32_t sbase = smem_u32(smem);
    int tid = threadIdx.x;
    int wid = tid >> 5, lane = tid & 31;
    int wm = wid & 1, wn = wid >> 1;        // 2 warps in M, 4 in N
    int q = lane >> 2, qi = lane & 3;
    long long bt0 = (long long)blockIdx.x * 64;

    float* par = (float*)(smem + PAR_OFF);
    if(tid < 192){
        par[tid]       = pw_b[layer*H + tid];
        par[192 + tid] = ln_g[layer*H + tid];
        par[384 + tid] = ln_b[layer*H + tid];
    }

    // A loader: 64 rows x 4 segs = 256 ids (one per thread) per dtype
    int rowA = tid >> 2, segA = tid & 3;
    uint32_t dstA = AR + (uint32_t)rowA*80 + (uint32_t)segA*16;
    const __nv_bfloat16* srcAh = g_yh + (bt0+rowA)*H + segA*8;
    const __nv_bfloat16* srcAl = g_yl + (bt0+rowA)*H + segA*8;

    // B loader: 1536 segs per chunk (2 dtypes x 192 rows x 4 segs), 6 per thread
    uint32_t dstB[6];
    #pragma unroll
    for(int m=0;m<6;m++){
        int id = tid + m*256;
        int d = id / 768;
        int rem = id - d*768;
        int o = rem >> 2, s = rem & 3;
        dstB[m] = BR + (uint32_t)d*BSTG_D + (uint32_t)o*80 + (uint32_t)s*16;
    }
    const uint4* wrp = (const uint4*)g_wr + (size_t)layer*9216 + tid;

#define ISSUE_CHUNK(cc, st) do { \
    uint32_t _as = sbase + (st)*ASTG; \
    CP16(_as + dstA,          srcAh + (cc)*32); \
    CP16(_as + dstA + ASTG_D, srcAl + (cc)*32); \
    uint32_t _bs = sbase + (st)*BSTG; \
    const uint4* _w = wrp + (cc)*1536; \
    _Pragma("unroll") \
    for(int m=0;m<6;m++) CP16(_bs + dstB[m], _w + m*256); \
    CP_COMMIT; \
} while(0)

    ISSUE_CHUNK(0, 0);
    ISSUE_CHUNK(1, 1);

    int g2 = lane >> 3, lr = lane & 7;
    uint32_t aOff[2];
    #pragma unroll
    for(int mt=0;mt<2;mt++)
        aOff[mt] = AR + (uint32_t)(wm*32 + mt*16 + (g2&1)*8 + lr)*80 + (uint32_t)(g2>>1)*16;
    uint32_t bOff[3];
    #pragma unroll
    for(int i=0;i<3;i++)
        bOff[i] = BR + (uint32_t)(wn*48 + i*16 + (g2>>1)*8 + lr)*80 + (uint32_t)(g2&1)*16;

    float acc[2][6][4];
    #pragma unroll
    for(int mt=0;mt<2;mt++)
        #pragma unroll
        for(int nt=0;nt<6;nt++)
            #pragma unroll
            for(int r=0;r<4;r++) acc[mt][nt][r] = 0.f;

    #pragma unroll 1
    for(int c=0;c<6;c++){
        if(c<5){ CP_WAIT1; } else { CP_WAIT0; }
        __syncthreads();
        int st = c & 1;
        uint32_t aH = sbase + st*ASTG;
        uint32_t bH = sbase + st*BSTG;
        #pragma unroll
        for(int ks=0;ks<2;ks++){
            uint32_t kOf = (uint32_t)ks*32;
            uint32_t ah[2][4], al[2][4], bb[3][4];
            LDSM4(ah[0], aH + aOff[0] + kOf);
            LDSM4(ah[1], aH + aOff[1] + kOf);
            LDSM4(al[0], aH + aOff[0] + ASTG_D + kOf);
            LDSM4(al[1], aH + aOff[1] + ASTG_D + kOf);
            #pragma unroll
            for(int i=0;i<3;i++) LDSM4(bb[i], bH + bOff[i] + kOf);
            #pragma unroll
            for(int mt=0;mt<2;mt++)
                #pragma unroll
                for(int i=0;i<3;i++){
                    MMA16816(acc[mt][2*i],   ah[mt], bb[i][0], bb[i][1]);
                    MMA16816(acc[mt][2*i+1], ah[mt], bb[i][2], bb[i][3]);
                    MMA16816(acc[mt][2*i],   al[mt], bb[i][0], bb[i][1]);
                    MMA16816(acc[mt][2*i+1], al[mt], bb[i][2], bb[i][3]);
                }
            #pragma unroll
            for(int i=0;i<3;i++) LDSM4(bb[i], bH + bOff[i] + BSTG_D + kOf);
            #pragma unroll
            for(int mt=0;mt<2;mt++)
                #pragma unroll
                for(int i=0;i<3;i++){
                    MMA16816(acc[mt][2*i],   ah[mt], bb[i][0], bb[i][1]);
                    MMA16816(acc[mt][2*i+1], ah[mt], bb[i][2], bb[i][3]);
                }
        }
        __syncthreads();
        if(c<4) ISSUE_CHUNK(c+2, st);
    }

    // ---------------- epilogue: bias + LN + gelu + residual ----------------
    float* red1 = (float*)(smem + AR);           // 256
    float* red2 = red1 + 256;                    // 256
    float* musm = red1 + 512;                    // 64
    float* rssm = red1 + 576;                    // 64

    float s1[2][2] = {{0.f,0.f},{0.f,0.f}};
    float s2[2][2] = {{0.f,0.f},{0.f,0.f}};
    #pragma unroll
    for(int mt=0;mt<2;mt++)
        #pragma unroll
        for(int nt=0;nt<6;nt++){
            int col = wn*48 + nt*8 + qi*2;
            float b0 = par[col], b1 = par[col+1];
            acc[mt][nt][0] += b0; acc[mt][nt][1] += b1;
            acc[mt][nt][2] += b0; acc[mt][nt][3] += b1;
            #pragma unroll
            for(int h=0;h<2;h++){
                float v0 = acc[mt][nt][h*2], v1 = acc[mt][nt][h*2+1];
                s1[mt][h] += v0 + v1;
                s2[mt][h] += v0*v0 + v1*v1;
            }
        }
    #pragma unroll
    for(int mt=0;mt<2;mt++)
        #pragma unroll
        for(int h=0;h<2;h++){
            float a = s1[mt][h], b2 = s2[mt][h];
            a  += __shfl_xor_sync(0xffffffffu, a, 1);
            a  += __shfl_xor_sync(0xffffffffu, a, 2);
            b2 += __shfl_xor_sync(0xffffffffu, b2, 1);
            b2 += __shfl_xor_sync(0xffffffffu, b2, 2);
            if(qi==0){
                int row = wm*32 + mt*16 + h*8 + q;
                red1[wn*64 + row] = a;
                red2[wn*64 + row] = b2;
            }
        }
    __syncthreads();
    if(tid < 64){
        float t1 = red1[tid] + red1[64+tid] + red1[128+tid] + red1[192+tid];
        float t2 = red2[tid] + red2[64+tid] + red2[128+tid] + red2[192+tid];
        float mu = t1*(1.0f/H);
        musm[tid] = mu;
        rssm[tid] = rsqrtf(t2*(1.0f/H) - mu*mu + 1e-5f);
    }
    __syncthreads();

    const float* lg = par + 192;
    const float* lb = par + 384;
    #pragma unroll
    for(int mt=0;mt<2;mt++)
        #pragma unroll
        for(int h=0;h<2;h++){
            int row = wm*32 + mt*16 + h*8 + q;
            float mu = musm[row], rs = rssm[row];
            float* xrow = g_x + (bt0+row)*H;
            __nv_bfloat16* yh = g_yh + (bt0+row)*H;
            __nv_bfloat16* yl = g_yl + (bt0+row)*H;
            #pragma unroll
            for(int nt=0;nt<6;nt++){
                int col = wn*48 + nt*8 + qi*2;
                float v0 = acc[mt][nt][h*2], v1 = acc[mt][nt][h*2+1];
                float2 res = *(float2*)(xrow + col);
                float o0 = gelu_exact((v0-mu)*rs*lg[col]   + lb[col])   + res.x;
                float o1 = gelu_exact((v1-mu)*rs*lg[col+1] + lb[col+1]) + res.y;
                *(float2*)(xrow + col) = make_float2(o0, o1);
                if(last){
                    __nv_bfloat16 h0 = __float2bfloat16(o0);
                    __nv_bfloat16 h1 = __float2bfloat16(o1);
                    __nv_bfloat16 l0 = __float2bfloat16(o0 - __bfloat162float(h0));
                    __nv_bfloat16 l1 = __float2bfloat16(o1 - __bfloat162float(h1));
                    __nv_bfloat162 ph = __halves2bfloat162(h0,h1);
                    __nv_bfloat162 pl = __halves2bfloat162(l0,l1);
                    *(__nv_bfloat162*)(yh + col) = ph;
                    *(__nv_bfloat162*)(yl + col) = pl;
                }
            }
        }
}

// ---------------------------------------------------------------------------
// spline: P = x_final . proj_w^T via split-bf16 mma, then RQ spline + logdet
#define SP_PWHI 0
#define SP_PWLO 12800
#define SP_ABUF 25600
#define SP_P    25600
#define SPLINE_SMEM_BYTES (25600 + 2*40960)

__global__ void __launch_bounds__(256) k_spline(
    const float* __restrict__ x, const float* __restrict__ xmask,
    const float* __restrict__ proj_b,
    float* __restrict__ out)
{
    extern __shared__ char smem[];
    uint32_t sbase = smem_u32(smem);
    int tid = threadIdx.x;
    int wid = tid >> 5, lane = tid & 31;
    int q = lane >> 2, qi = lane & 3;
    long long bt0 = (long long)blockIdx.x * 256;

    {
        const uint4* src = (const uint4*)g_pw;
        uint4* dst = (uint4*)smem;
        #pragma unroll
        for(int i=tid;i<1600;i+=256) dst[i] = src[i];
    }

    int rows[4], segs[4];
    #pragma unroll
    for(int m=0;m<4;m++){
        int id = tid + m*256;
        rows[m] = id >> 2; segs[m] = id & 3;
    }

#define SP_ISSUE(cc, st) do { \
    uint32_t _ah = sbase + SP_ABUF + (st)*40960; \
    uint32_t _al = _ah + 20480; \
    int _k = (cc)*32; \
    _Pragma("unroll") \
    for(int m=0;m<4;m++){ \
        uint32_t d = (uint32_t)rows[m]*80 + (uint32_t)segs[m]*16; \
        CP16(_ah + d, g_yh + (bt0+rows[m])*H + segs[m]*8 + _k); \
        CP16(_al + d, g_yl + (bt0+rows[m])*H + segs[m]*8 + _k); \
    } \
    CP_COMMIT; \
} while(0)

    SP_ISSUE(0, 0);
    SP_ISSUE(1, 1);

    int g2 = lane >> 3, lr = lane & 7;
    uint32_t aOff[2];
    #pragma unroll
    for(int mt=0;mt<2;mt++)
        aOff[mt] = (uint32_t)(wid*32 + mt*16 + (g2&1)*8 + lr)*80 + (uint32_t)(g2>>1)*16;
    uint32_t bOff[2];
    #pragma unroll
    for(int i=0;i<2;i++)
        bOff[i] = (uint32_t)(i*16 + (g2>>1)*8 + lr)*400 + (uint32_t)(g2&1)*16;

    float acc[2][4][4];
    #pragma unroll
    for(int mt=0;mt<2;mt++)
        #pragma unroll
        for(int nt=0;nt<4;nt++)
            #pragma unroll
            for(int r=0;r<4;r++) acc[mt][nt][r]=0.f;

    #pragma unroll 1
    for(int c=0;c<6;c++){
        if(c<5){ CP_WAIT1; } else { CP_WAIT0; }
        __syncthreads();
        uint32_t abufH = sbase + SP_ABUF + (c&1)*40960;
        uint32_t abufL = abufH + 20480;
        #pragma unroll
        for(int ks=0;ks<2;ks++){
            uint32_t kA = ks*32;
            uint32_t kB = (uint32_t)c*64 + ks*32;
            uint32_t ah[2][4], al[2][4], bb[2][4];
            LDSM4(ah[0], abufH + aOff[0] + kA);
            LDSM4(ah[1], abufH + aOff[1] + kA);
            LDSM4(al[0], abufL + aOff[0] + kA);
            LDSM4(al[1], abufL + aOff[1] + kA);
            LDSM4(bb[0], sbase + SP_PWHI + bOff[0] + kB);
            LDSM4(bb[1], sbase + SP_PWHI + bOff[1] + kB);
            #pragma unroll
            for(int mt=0;mt<2;mt++)
                #pragma unroll
                for(int i=0;i<2;i++){
                    MMA16816(acc[mt][2*i],   ah[mt], bb[i][0], bb[i][1]);
                    MMA16816(acc[mt][2*i+1], ah[mt], bb[i][2], bb[i][3]);
                    MMA16816(acc[mt][2*i],   al[mt], bb[i][0], bb[i][1]);
                    MMA16816(acc[mt][2*i+1], al[mt], bb[i][2], bb[i][3]);
                }
            LDSM4(bb[0], sbase + SP_PWLO + bOff[0] + kB);
            LDSM4(bb[1], sbase + SP_PWLO + bOff[1] + kB);
            #pragma unroll
            for(int mt=0;mt<2;mt++)
                #pragma unroll
                for(int i=0;i<2;i++){
                    MMA16816(acc[mt][2*i],   ah[mt], bb[i][0], bb[i][1]);
                    MMA16816(acc[mt][2*i+1], ah[mt], bb[i][2], bb[i][3]);
                }
        }
        __syncthreads();
        if(c<4) SP_ISSUE(c+2, c&1);
    }

    float* Psm = (float*)(smem + SP_P);
    #pragma unroll
    for(int mt=0;mt<2;mt++)
        #pragma unroll
        for(int h=0;h<2;h++){
            int row = wid*32 + mt*16 + h*8 + q;
            #pragma unroll
            for(int nt=0;nt<4;nt++){
                int col = nt*8 + qi*2;
                Psm[row*33 + col]   = acc[mt][nt][h*2];
                Psm[row*33 + col+1] = acc[mt][nt][h*2+1];
            }
        }
    __syncthreads();

    int b = (int)(bt0 >> 13);
    int t = (int)(bt0 & (T-1)) + tid;
    float mask = xmask[(long long)b*T + t];

    float p[NJ];
    #pragma unroll
    for(int j=0;j<NJ;j++) p[j] = (Psm[tid*33 + j] + __ldg(proj_b + j)) * mask;

    const float inv_dn = 0.07216878364870323f;   // 1/sqrt(192)

    float cwv[BINS+1], wsv[BINS];
    {
        float m = -1e30f;
        #pragma unroll
        for(int j=0;j<BINS;j++) m = fmaxf(m, p[j]);
        float e[BINS]; float ssum = 0.f;
        #pragma unroll
        for(int j=0;j<BINS;j++){ e[j] = expf((p[j]-m)*inv_dn); ssum += e[j]; }
        float inv = 1.0f/ssum;
        float cum = 0.f;
        cwv[0] = -TAILV;
        #pragma unroll
        for(int j=0;j<BINS;j++){
            float wj = 1e-3f + 0.99f*e[j]*inv;
            cum += wj;
            cwv[j+1] = 2.0f*TAILV*cum - TAILV;
        }
        cwv[BINS] = TAILV;
        #pragma unroll
        for(int j=0;j<BINS;j++) wsv[j] = cwv[j+1]-cwv[j];
    }
    float chv[BINS+1], hsv[BINS];
    {
        float m = -1e30f;
        #pragma unroll
        for(int j=0;j<BINS;j++) m = fmaxf(m, p[BINS+j]);
        float e[BINS]; float ssum = 0.f;
        #pragma unroll
        for(int j=0;j<BINS;j++){ e[j] = expf((p[BINS+j]-m)*inv_dn); ssum += e[j]; }
        float inv = 1.0f/ssum;
        float cum = 0.f;
        chv[0] = -TAILV;
        #pragma unroll
        for(int j=0;j<BINS;j++){
            float hj = 1e-3f + 0.99f*e[j]*inv;
            cum += hj;
            chv[j+1] = 2.0f*TAILV*cum - TAILV;
        }
        chv[BINS] = TAILV;
        #pragma unroll
        for(int j=0;j<BINS;j++) hsv[j] = chv[j+1]-chv[j];
    }
    float derv[BINS+1];
    derv[0] = 1.0f; derv[BINS] = 1.0f;
    #pragma unroll
    for(int k=1;k<BINS;k++){
        float u = p[2*BINS + k - 1];
        float sp = (u > 20.f) ? u : log1pf(expf(u));
        derv[k] = 1e-3f + sp;
    }

    float xbv = x[((long long)b*2+1)*T + t];
    bool inside = (xbv >= -TAILV) && (xbv <= TAILV);
    float xc = fminf(fmaxf(xbv, -TAILV), TAILV);
    int idx = 0;
    #pragma unroll
    for(int j=0;j<BINS;j++) idx += (xc >= cwv[j]) ? 1 : 0;
    idx -= 1;
    idx = max(0, min(BINS-1, idx));

    float icw=0.f, ibw=1.f, ich=0.f, ih=1.f, dk=1.f, dk1=1.f;
    #pragma unroll
    for(int j=0;j<BINS;j++){
        bool sel = (idx==j);
        icw = sel ? cwv[j]   : icw;
        ibw = sel ? wsv[j]   : ibw;
        ich = sel ? chv[j]   : ich;
        ih  = sel ? hsv[j]   : ih;
        dk  = sel ? derv[j]  : dk;
        dk1 = sel ? derv[j+1]: dk1;
    }

    float idl = ih/ibw;
    float th  = (xc - icw)/ibw;
    float t1m = th*(1.0f - th);
    float num = ih*(idl*th*th + dk*t1m);
    float den = idl + (dk + dk1 - 2.0f*idl)*t1m;
    float outv = ich + num/den;
    float omt = 1.0f - th;
    float dnum = idl*idl*(dk1*th*th + 2.0f*idl*t1m + dk*omt*omt);
    float lad = logf(dnum) - 2.0f*logf(den);

    float xb2 = inside ? outv : xbv;
    lad = inside ? lad : 0.0f;

    float xav = x[((long long)b*2)*T + t];
    out[(long long)b*2*T + t]     = xav*mask;
    out[(long long)b*2*T + T + t] = xb2*mask;

    float lv = lad*mask;
    #pragma unroll
    for(int o=16;o>0;o>>=1) lv += __shfl_xor_sync(0xffffffffu, lv, o);
    static __shared__ float red8[8];
    if(lane == 0) red8[wid] = lv;
    __syncthreads();
    if(tid == 0){
        float acc8 = red8[0]+red8[1]+red8[2]+red8[3]+red8[4]+red8[5]+red8[6]+red8[7];
        atomicAdd(out + (long long)B*2*T + b, acc8);
    }
}

// ---------------------------------------------------------------------------
extern "C" void kernel_launch(void* const* d_in, const int* in_sizes, int n_in,
                              void* d_out, int out_size)
{
    const float* x      = (const float*)d_in[0];
    const float* xmask  = (const float*)d_in[1];
    const float* in_w   = (const float*)d_in[2];
    const float* in_b   = (const float*)d_in[3];
    const float* dw_w   = (const float*)d_in[4];
    const float* dw_b   = (const float*)d_in[5];
    const float* ln1_g  = (const float*)d_in[6];
    const float* ln1_b  = (const float*)d_in[7];
    const float* pw_w   = (const float*)d_in[8];
    const float* pw_b   = (const float*)d_in[9];
    const float* ln2_g  = (const float*)d_in[10];
    const float* ln2_b  = (const float*)d_in[11];
    const float* proj_w = (const float*)d_in[12];
    const float* proj_b = (const float*)d_in[13];
    float* out = (float*)d_out;

    cudaFuncSetAttribute(k_gemm_mma, cudaFuncAttributeMaxDynamicSharedMemorySize, GEMM_SMEM_BYTES);
    cudaFuncSetAttribute(k_spline,   cudaFuncAttributeMaxDynamicSharedMemorySize, SPLINE_SMEM_BYTES);

    k_zero<<<1, 32>>>(out);
    k_prep<<<(3*H*H + 255)/256, 256>>>(pw_w, proj_w, dw_w);
    int dil = 1;
    for(int L=0; L<3; L++){
        k_conv<<<BT/32, 256>>>(L, dil, x, in_w, in_b, xmask, dw_b, ln1_g, ln1_b);
        k_gemm_mma<<<BT/64, 256, GEMM_SMEM_BYTES>>>(L, (L==2)?1:0, pw_b, ln2_g, ln2_b);
        dil *= 3;
    }
    k_spline<<<BT/256, 256, SPLINE_SMEM_BYTES>>>(x, xmask, proj_b, out);
}